// round 1
// baseline (speedup 1.0000x reference)
#include <cuda_runtime.h>
#include <math.h>

#define BB 2
#define HH 16
#define NSEQ 2048
#define DD 64
#define CC 1024
#define MM (BB*NSEQ)      /* 4096 */
#define K3 (3*CC)         /* 3072 */

// Scratch (allocation-free rule: __device__ globals)
__device__ float g_q[BB*HH*NSEQ*DD];
__device__ float g_k[BB*HH*NSEQ*DD];
__device__ float g_v[BB*HH*NSEQ*DD];
__device__ float g_att[MM*CC];

// ---------------------------------------------------------------------------
// QKV GEMM: qkv = x[M,C] @ W_qkv[C,3C] + b_qkv, scattered into Q/K/V [B,H,N,D]
// 64x64 tile, K-tile 16, 256 threads, 4x4 micro-tile per thread.
// ---------------------------------------------------------------------------
__global__ __launch_bounds__(256) void qkv_gemm_kernel(
    const float* __restrict__ A, const float* __restrict__ Bw,
    const float* __restrict__ bias)
{
    __shared__ float As[64][17];
    __shared__ float Bs[16][64];

    const int tid = threadIdx.x;
    const int tx = tid & 15, ty = tid >> 4;
    const int m0 = blockIdx.y * 64;
    const int n0 = blockIdx.x * 64;

    const int ar = tid >> 2, ac = (tid & 3) * 4;   // A tile load coords
    const int br = tid >> 4, bc = (tid & 15) * 4;  // B tile load coords

    float acc[4][4];
    #pragma unroll
    for (int i = 0; i < 4; i++)
        #pragma unroll
        for (int j = 0; j < 4; j++) acc[i][j] = 0.f;

    for (int k0 = 0; k0 < CC; k0 += 16) {
        float4 av = *(const float4*)&A[(m0 + ar) * CC + k0 + ac];
        As[ar][ac + 0] = av.x; As[ar][ac + 1] = av.y;
        As[ar][ac + 2] = av.z; As[ar][ac + 3] = av.w;
        *(float4*)&Bs[br][bc] = *(const float4*)&Bw[(k0 + br) * K3 + n0 + bc];
        __syncthreads();

        #pragma unroll
        for (int kk = 0; kk < 16; kk++) {
            float4 b4 = *(float4*)&Bs[kk][tx * 4];
            float bb[4] = {b4.x, b4.y, b4.z, b4.w};
            float aa[4];
            #pragma unroll
            for (int i = 0; i < 4; i++) aa[i] = As[ty * 4 + i][kk];
            #pragma unroll
            for (int i = 0; i < 4; i++)
                #pragma unroll
                for (int j = 0; j < 4; j++)
                    acc[i][j] = fmaf(aa[i], bb[j], acc[i][j]);
        }
        __syncthreads();
    }

    // Scatter epilogue: col jj = n0 + tx*4 + j  -> (s, h, dd); tile is 64-aligned
    // so s and h are constant per block.
    const int s = n0 >> 10;
    const int h = (n0 & 1023) >> 6;
    float* dst = (s == 0) ? g_q : ((s == 1) ? g_k : g_v);

    #pragma unroll
    for (int i = 0; i < 4; i++) {
        int m = m0 + ty * 4 + i;
        int b = m >> 11;          // m / NSEQ
        int n = m & (NSEQ - 1);
        float4 o4;
        float* po = &o4.x;
        #pragma unroll
        for (int j = 0; j < 4; j++) {
            int dd = tx * 4 + j;
            po[j] = acc[i][j] + bias[n0 + dd];
        }
        *(float4*)&dst[((b * HH + h) * NSEQ + n) * DD + tx * 4] = o4;
    }
}

// ---------------------------------------------------------------------------
// Plain GEMM + bias: C[M,Nn] = A[M,Cin] @ Bw[Cin,Nn] + bias
// ---------------------------------------------------------------------------
__global__ __launch_bounds__(256) void gemm_bias_kernel(
    const float* __restrict__ A, const float* __restrict__ Bw,
    const float* __restrict__ bias, float* __restrict__ Cout,
    int Nn, int Kin)
{
    __shared__ float As[64][17];
    __shared__ float Bs[16][64];

    const int tid = threadIdx.x;
    const int tx = tid & 15, ty = tid >> 4;
    const int m0 = blockIdx.y * 64;
    const int n0 = blockIdx.x * 64;

    const int ar = tid >> 2, ac = (tid & 3) * 4;
    const int br = tid >> 4, bc = (tid & 15) * 4;

    float acc[4][4];
    #pragma unroll
    for (int i = 0; i < 4; i++)
        #pragma unroll
        for (int j = 0; j < 4; j++) acc[i][j] = 0.f;

    for (int k0 = 0; k0 < Kin; k0 += 16) {
        float4 av = *(const float4*)&A[(m0 + ar) * Kin + k0 + ac];
        As[ar][ac + 0] = av.x; As[ar][ac + 1] = av.y;
        As[ar][ac + 2] = av.z; As[ar][ac + 3] = av.w;
        *(float4*)&Bs[br][bc] = *(const float4*)&Bw[(k0 + br) * Nn + n0 + bc];
        __syncthreads();

        #pragma unroll
        for (int kk = 0; kk < 16; kk++) {
            float4 b4 = *(float4*)&Bs[kk][tx * 4];
            float bb[4] = {b4.x, b4.y, b4.z, b4.w};
            float aa[4];
            #pragma unroll
            for (int i = 0; i < 4; i++) aa[i] = As[ty * 4 + i][kk];
            #pragma unroll
            for (int i = 0; i < 4; i++)
                #pragma unroll
                for (int j = 0; j < 4; j++)
                    acc[i][j] = fmaf(aa[i], bb[j], acc[i][j]);
        }
        __syncthreads();
    }

    #pragma unroll
    for (int i = 0; i < 4; i++) {
        int m = m0 + ty * 4 + i;
        float4 o4;
        float* po = &o4.x;
        #pragma unroll
        for (int j = 0; j < 4; j++)
            po[j] = acc[i][j] + bias[n0 + tx * 4 + j];
        *(float4*)&Cout[m * Nn + n0 + tx * 4] = o4;
    }
}

// ---------------------------------------------------------------------------
// Flash attention (fp32): per (b,h), Br=Bc=64, d=64.
// Writes output directly to [B, N, C] layout (fused transpose).
// ---------------------------------------------------------------------------
#define FPAD 68
#define SM_FLASH_BYTES ((4 * 64 * FPAD + 128) * 4)

__global__ __launch_bounds__(256) void flash_attn_kernel(
    const float* __restrict__ Qg, const float* __restrict__ Kg,
    const float* __restrict__ Vg, float* __restrict__ out)
{
    extern __shared__ float sm[];
    float (*Qs)[FPAD]  = (float(*)[FPAD])(sm);
    float (*KsT)[FPAD] = (float(*)[FPAD])(sm + 64 * FPAD);      // [d][n]
    float (*Vs)[FPAD]  = (float(*)[FPAD])(sm + 2 * 64 * FPAD);  // [n][d]
    float (*Ss)[FPAD]  = (float(*)[FPAD])(sm + 3 * 64 * FPAD);  // scores
    float* row_alpha   = sm + 4 * 64 * FPAD;                    // [64]
    float* row_scale   = row_alpha + 64;                        // [64]

    const int tid = threadIdx.x;
    const int tx = tid & 15, ty = tid >> 4;
    const int bh = blockIdx.y;                 // b*H + h
    const int q0 = blockIdx.x * 64;
    const long base = (long)bh * NSEQ * DD;

    // Load Q tile [64 x 64]
    #pragma unroll
    for (int t = 0; t < 4; t++) {
        int idx = tid + t * 256;
        int r = idx >> 4, c4 = (idx & 15) * 4;
        *(float4*)&Qs[r][c4] = *(const float4*)&Qg[base + (q0 + r) * DD + c4];
    }

    float o[4][4];
    #pragma unroll
    for (int i = 0; i < 4; i++)
        #pragma unroll
        for (int j = 0; j < 4; j++) o[i][j] = 0.f;

    float m_i = -1e30f, l_i = 0.f;  // valid for tid < 64 (row owners)

    const float scale = 0.125f;     // 1/sqrt(64)

    for (int kc = 0; kc < NSEQ / 64; kc++) {
        __syncthreads();  // protect Ks/Vs/Ss from previous iteration readers

        // Load K (transposed into KsT[d][n]) and V (natural [n][d])
        #pragma unroll
        for (int t = 0; t < 4; t++) {
            int idx = tid + t * 256;
            int r = idx >> 4, c4 = (idx & 15) * 4;
            float4 kv = *(const float4*)&Kg[base + (kc * 64 + r) * DD + c4];
            KsT[c4 + 0][r] = kv.x; KsT[c4 + 1][r] = kv.y;
            KsT[c4 + 2][r] = kv.z; KsT[c4 + 3][r] = kv.w;
            *(float4*)&Vs[r][c4] = *(const float4*)&Vg[base + (kc * 64 + r) * DD + c4];
        }
        __syncthreads();

        // S = (Q @ K^T) * scale
        float s[4][4];
        #pragma unroll
        for (int i = 0; i < 4; i++)
            #pragma unroll
            for (int j = 0; j < 4; j++) s[i][j] = 0.f;

        #pragma unroll 8
        for (int kk = 0; kk < 64; kk++) {
            float4 k4 = *(float4*)&KsT[kk][tx * 4];
            float kb[4] = {k4.x, k4.y, k4.z, k4.w};
            float qa[4];
            #pragma unroll
            for (int i = 0; i < 4; i++) qa[i] = Qs[ty * 4 + i][kk];
            #pragma unroll
            for (int i = 0; i < 4; i++)
                #pragma unroll
                for (int j = 0; j < 4; j++)
                    s[i][j] = fmaf(qa[i], kb[j], s[i][j]);
        }
        #pragma unroll
        for (int i = 0; i < 4; i++) {
            float4 s4 = make_float4(s[i][0] * scale, s[i][1] * scale,
                                    s[i][2] * scale, s[i][3] * scale);
            *(float4*)&Ss[ty * 4 + i][tx * 4] = s4;
        }
        __syncthreads();

        // Online softmax: one thread per row (tid < 64)
        if (tid < 64) {
            int r = tid;
            float mx = m_i;
            #pragma unroll 8
            for (int c = 0; c < 64; c++) mx = fmaxf(mx, Ss[r][c]);
            float alpha = __expf(m_i - mx);
            float sum = 0.f;
            #pragma unroll 8
            for (int c = 0; c < 64; c++) {
                float p = __expf(Ss[r][c] - mx);
                Ss[r][c] = p;
                sum += p;
            }
            l_i = l_i * alpha + sum;
            m_i = mx;
            row_alpha[r] = alpha;
        }
        __syncthreads();

        // O = O*alpha + P @ V
        float al[4];
        #pragma unroll
        for (int i = 0; i < 4; i++) al[i] = row_alpha[ty * 4 + i];
        #pragma unroll
        for (int i = 0; i < 4; i++)
            #pragma unroll
            for (int j = 0; j < 4; j++) o[i][j] *= al[i];

        #pragma unroll 8
        for (int kk = 0; kk < 64; kk++) {
            float4 v4 = *(float4*)&Vs[kk][tx * 4];
            float vb[4] = {v4.x, v4.y, v4.z, v4.w};
            float pa[4];
            #pragma unroll
            for (int i = 0; i < 4; i++) pa[i] = Ss[ty * 4 + i][kk];
            #pragma unroll
            for (int i = 0; i < 4; i++)
                #pragma unroll
                for (int j = 0; j < 4; j++)
                    o[i][j] = fmaf(pa[i], vb[j], o[i][j]);
        }
    }

    if (tid < 64) row_scale[tid] = 1.f / l_i;
    __syncthreads();

    // Write out[b, n, h*64 + dd]
    const int b = bh >> 4;
    const int h = bh & 15;
    #pragma unroll
    for (int i = 0; i < 4; i++) {
        int r = ty * 4 + i;
        float sc = row_scale[r];
        int n = q0 + r;
        float4 o4 = make_float4(o[i][0] * sc, o[i][1] * sc,
                                o[i][2] * sc, o[i][3] * sc);
        *(float4*)&out[((long)(b * NSEQ + n)) * CC + h * 64 + tx * 4] = o4;
    }
}

// ---------------------------------------------------------------------------
// Launcher
// ---------------------------------------------------------------------------
extern "C" void kernel_launch(void* const* d_in, const int* in_sizes, int n_in,
                              void* d_out, int out_size)
{
    const float* x     = (const float*)d_in[0];
    const float* W_qkv = (const float*)d_in[1];
    const float* b_qkv = (const float*)d_in[2];
    const float* W_out = (const float*)d_in[3];
    const float* b_out = (const float*)d_in[4];
    float* out = (float*)d_out;

    float* q; float* k; float* v; float* att;
    cudaGetSymbolAddress((void**)&q,   g_q);
    cudaGetSymbolAddress((void**)&k,   g_k);
    cudaGetSymbolAddress((void**)&v,   g_v);
    cudaGetSymbolAddress((void**)&att, g_att);

    cudaFuncSetAttribute(flash_attn_kernel,
                         cudaFuncAttributeMaxDynamicSharedMemorySize,
                         SM_FLASH_BYTES);

    // 1) QKV projection + scatter
    {
        dim3 grid(K3 / 64, MM / 64);
        qkv_gemm_kernel<<<grid, 256>>>(x, W_qkv, b_qkv);
    }
    // 2) Attention per (b,h), flash-style
    {
        dim3 grid(NSEQ / 64, BB * HH);
        flash_attn_kernel<<<grid, 256, SM_FLASH_BYTES>>>(q, k, v, att);
    }
    // 3) Output projection
    {
        dim3 grid(CC / 64, MM / 64);
        gemm_bias_kernel<<<grid, 256>>>(att, W_out, b_out, out, CC, CC);
    }
}

// round 3
// speedup vs baseline: 3.6328x; 3.6328x over previous
#include <cuda_runtime.h>
#include <cuda_bf16.h>
#include <cuda_fp16.h>
#include <math.h>
#include <stdint.h>

#define BB 2
#define HH 16
#define NSEQ 2048
#define DD 64
#define CC 1024
#define MM (BB*NSEQ)      /* 4096 */
#define K3 (3*CC)         /* 3072 */
#define GK 3072           /* K' = 3*1024 for bf16x3 split */

// ---------------------------------------------------------------------------
// Scratch (__device__ globals; allocation-free rule)
// ---------------------------------------------------------------------------
__device__ __align__(256) __half g_qh[(size_t)BB*HH*NSEQ*DD];   // Q fp16, pre-scaled by 0.125
__device__ __align__(256) __half g_kh[(size_t)BB*HH*NSEQ*DD];
__device__ __align__(256) __half g_vh[(size_t)BB*HH*NSEQ*DD];
__device__ __align__(256) __nv_bfloat16 g_Abuf[(size_t)MM*GK];  // A' = [hi|hi|lo]
__device__ __align__(256) __nv_bfloat16 g_Bq[(size_t)K3*GK];    // W_qkv' rows n: [hi;lo;hi]
__device__ __align__(256) __nv_bfloat16 g_Bo[(size_t)CC*GK];    // W_out'

// ---------------------------------------------------------------------------
// PTX helpers (baseline sm_80 ISA only — no 'a'-target features)
// ---------------------------------------------------------------------------
__device__ __forceinline__ uint32_t smem_u32(const void* p) {
    uint32_t a;
    asm("{ .reg .u64 t; cvta.to.shared.u64 t, %1; cvt.u32.u64 %0, t; }"
        : "=r"(a) : "l"(p));
    return a;
}

#define SW128(off) ((off) ^ (((off) >> 3) & 0x70))

#define CP16(dst, src) \
    asm volatile("cp.async.cg.shared.global [%0], [%1], 16;" :: "r"(dst), "l"(src))
#define CP_COMMIT() asm volatile("cp.async.commit_group;" ::: "memory")
#define CP_WAIT0()  asm volatile("cp.async.wait_group 0;" ::: "memory")

__device__ __forceinline__ void ldsm4(uint32_t& r0, uint32_t& r1,
                                      uint32_t& r2, uint32_t& r3, uint32_t a) {
    asm volatile("ldmatrix.sync.aligned.m8n8.x4.shared.b16 {%0,%1,%2,%3}, [%4];"
        : "=r"(r0), "=r"(r1), "=r"(r2), "=r"(r3) : "r"(a));
}
__device__ __forceinline__ void ldsm2t(uint32_t& r0, uint32_t& r1, uint32_t a) {
    asm volatile("ldmatrix.sync.aligned.m8n8.x2.trans.shared.b16 {%0,%1}, [%2];"
        : "=r"(r0), "=r"(r1) : "r"(a));
}
__device__ __forceinline__ void mma_bf16(float* c, const uint32_t* a, uint32_t b0, uint32_t b1) {
    asm volatile("mma.sync.aligned.m16n8k16.row.col.f32.bf16.bf16.f32 "
        "{%0,%1,%2,%3}, {%4,%5,%6,%7}, {%8,%9}, {%0,%1,%2,%3};"
        : "+f"(c[0]), "+f"(c[1]), "+f"(c[2]), "+f"(c[3])
        : "r"(a[0]), "r"(a[1]), "r"(a[2]), "r"(a[3]), "r"(b0), "r"(b1));
}
__device__ __forceinline__ void mma_f16(float* c, const uint32_t* a, uint32_t b0, uint32_t b1) {
    asm volatile("mma.sync.aligned.m16n8k16.row.col.f32.f16.f16.f32 "
        "{%0,%1,%2,%3}, {%4,%5,%6,%7}, {%8,%9}, {%0,%1,%2,%3};"
        : "+f"(c[0]), "+f"(c[1]), "+f"(c[2]), "+f"(c[3])
        : "r"(a[0]), "r"(a[1]), "r"(a[2]), "r"(a[3]), "r"(b0), "r"(b1));
}

__device__ __forceinline__ uint32_t pack_h2(float lo, float hi) {
    __half2 h = __float22half2_rn(make_float2(lo, hi));
    return *(uint32_t*)&h;
}

// ---------------------------------------------------------------------------
// Prep: split fp32 [M][1024] -> bf16 [M][3072] = [hi | hi | lo]
// ---------------------------------------------------------------------------
__global__ __launch_bounds__(256) void split_x_kernel(
    const float* __restrict__ in, __nv_bfloat16* __restrict__ out)
{
    int idx = blockIdx.x * 256 + threadIdx.x;
    int row = idx >> 9;
    int c2 = (idx & 511) * 2;
    float2 v = *(const float2*)&in[(size_t)row * 1024 + c2];
    __nv_bfloat162 hi, lo;
    hi.x = __float2bfloat16_rn(v.x);
    hi.y = __float2bfloat16_rn(v.y);
    lo.x = __float2bfloat16_rn(v.x - __bfloat162float(hi.x));
    lo.y = __float2bfloat16_rn(v.y - __bfloat162float(hi.y));
    __nv_bfloat162* o = (__nv_bfloat162*)(out + (size_t)row * GK);
    int p = c2 >> 1;
    o[p]        = hi;
    o[512 + p]  = hi;
    o[1024 + p] = lo;
}

// ---------------------------------------------------------------------------
// Prep: W [K][N] fp32 -> B' [N][3K] bf16 K-major, blocks [hi ; lo ; hi]
// ---------------------------------------------------------------------------
__global__ void transw_kernel(const float* __restrict__ W,
                              __nv_bfloat16* __restrict__ Bo, int K, int N)
{
    __shared__ float t[32][33];
    int k0 = blockIdx.x * 32, n0 = blockIdx.y * 32;
    int tx = threadIdx.x, ty = threadIdx.y;   // (32, 8)
    #pragma unroll
    for (int i = 0; i < 4; i++)
        t[ty + i * 8][tx] = W[(size_t)(k0 + ty + i * 8) * N + n0 + tx];
    __syncthreads();
    #pragma unroll
    for (int i = 0; i < 4; i++) {
        int n = n0 + ty + i * 8, k = k0 + tx;
        float v = t[tx][ty + i * 8];
        __nv_bfloat16 hi = __float2bfloat16_rn(v);
        __nv_bfloat16 lo = __float2bfloat16_rn(v - __bfloat162float(hi));
        __nv_bfloat16* row = Bo + (size_t)n * (3 * K);
        row[k]         = hi;
        row[K + k]     = lo;
        row[2 * K + k] = hi;
    }
}

// ---------------------------------------------------------------------------
// HMMA GEMM: D[M][N] = A'[M][GK] @ B'[N][GK]^T (+bias)
// BM=128, BN=128, BK=64. 8 warps: 4(m) x 2(n) -> warp tile 32x64.
// MODE 0: qkv — write fp16 to g_qh/g_kh/g_vh in [b,h,n,d], Q pre-scaled 0.125.
// MODE 1: out proj — write fp32 + bias to Cout.
// ---------------------------------------------------------------------------
#define GEMM_SMEM (4 * 16384 + 128)
#define KITERS (GK / 64)

template<int MODE>
__global__ __launch_bounds__(256, 1) void mma_gemm_kernel(
    const __nv_bfloat16* __restrict__ A,
    const __nv_bfloat16* __restrict__ Bm,
    const float* __restrict__ bias,
    float* __restrict__ Cout,
    __half* __restrict__ Qh, __half* __restrict__ Kh, __half* __restrict__ Vh)
{
    extern __shared__ char smraw[];
    char* smp = (char*)(((uintptr_t)smraw + 127) & ~(uintptr_t)127);
    const uint32_t sb = smem_u32(smp);

    const int tid = threadIdx.x;
    const int lane = tid & 31, wid = tid >> 5;
    const int wm = wid & 3, wn = wid >> 2;
    const int m0 = blockIdx.y * 128;
    const int n0 = blockIdx.x * 128;

    // smem offsets: [A0 | B0 | A1 | B1], 16KB each
    const uint32_t aoff[2] = {0u, 32768u};
    const uint32_t boff[2] = {16384u, 49152u};

    const char* gA = (const char*)A + (size_t)m0 * (GK * 2);
    const char* gB = (const char*)Bm + (size_t)n0 * (GK * 2);

    // chunk coords for cp.async (16B chunks, 8 per 128B row)
    const int crow = tid >> 3;          // 0..31 step: +32 per i
    const int ccol = (tid & 7) * 16;

    auto load_tile = [&](int it, int buf) {
        const size_t kbyte = (size_t)it * 128;
        #pragma unroll
        for (int i = 0; i < 4; i++) {
            int r = crow + i * 32;
            CP16(sb + aoff[buf] + SW128(r * 128 + ccol),
                 gA + (size_t)r * (GK * 2) + kbyte + ccol);
        }
        #pragma unroll
        for (int i = 0; i < 4; i++) {
            int r = crow + i * 32;
            CP16(sb + boff[buf] + SW128(r * 128 + ccol),
                 gB + (size_t)r * (GK * 2) + kbyte + ccol);
        }
    };

    float acc[2][8][4];
    #pragma unroll
    for (int mt = 0; mt < 2; mt++)
        #pragma unroll
        for (int nt = 0; nt < 8; nt++)
            #pragma unroll
            for (int j = 0; j < 4; j++) acc[mt][nt][j] = 0.f;

    load_tile(0, 0);
    CP_COMMIT();

    for (int it = 0; it < KITERS; it++) {
        CP_WAIT0();
        __syncthreads();
        if (it + 1 < KITERS) {
            load_tile(it + 1, (it + 1) & 1);
            CP_COMMIT();
        }
        const int buf = it & 1;

        #pragma unroll
        for (int ks = 0; ks < 4; ks++) {
            uint32_t a[2][4];
            #pragma unroll
            for (int mt = 0; mt < 2; mt++) {
                uint32_t addr = sb + aoff[buf] +
                    SW128((wm * 32 + mt * 16 + (lane & 15)) * 128 +
                          ks * 32 + ((lane >> 4) << 4));
                ldsm4(a[mt][0], a[mt][1], a[mt][2], a[mt][3], addr);
            }
            uint32_t b[8][2];
            #pragma unroll
            for (int p = 0; p < 4; p++) {
                uint32_t addr = sb + boff[buf] +
                    SW128((wn * 64 + p * 16 + (lane & 7) + ((lane >> 4) & 1) * 8) * 128 +
                          ks * 32 + ((lane >> 3) & 1) * 16);
                ldsm4(b[2 * p][0], b[2 * p][1], b[2 * p + 1][0], b[2 * p + 1][1], addr);
            }
            #pragma unroll
            for (int mt = 0; mt < 2; mt++)
                #pragma unroll
                for (int nt = 0; nt < 8; nt++)
                    mma_bf16(acc[mt][nt], a[mt], b[nt][0], b[nt][1]);
        }
        __syncthreads();
    }

    // ---------------- epilogue ----------------
    const int colbase = n0 + wn * 64;   // 64-aligned -> single head per warp
    if (MODE == 0) {
        const int s = colbase >> 10;
        const int h = (colbase >> 6) & 15;
        __half* dst = (s == 0) ? Qh : ((s == 1) ? Kh : Vh);
        const float scl = (s == 0) ? 0.125f : 1.0f;
        #pragma unroll
        for (int mt = 0; mt < 2; mt++) {
            #pragma unroll
            for (int hf = 0; hf < 2; hf++) {
                int r = m0 + wm * 32 + mt * 16 + (lane >> 2) + hf * 8;
                int bidx = r >> 11, n = r & (NSEQ - 1);
                size_t rowoff = (((size_t)bidx * HH + h) * NSEQ + n) * DD;
                #pragma unroll
                for (int nt = 0; nt < 8; nt++) {
                    int dd = nt * 8 + (lane & 3) * 2;
                    float v0 = (acc[mt][nt][hf * 2 + 0] + bias[colbase + dd]) * scl;
                    float v1 = (acc[mt][nt][hf * 2 + 1] + bias[colbase + dd + 1]) * scl;
                    __half2 h2 = __float22half2_rn(make_float2(v0, v1));
                    *(__half2*)&dst[rowoff + dd] = h2;
                }
            }
        }
    } else {
        #pragma unroll
        for (int mt = 0; mt < 2; mt++) {
            #pragma unroll
            for (int hf = 0; hf < 2; hf++) {
                int r = m0 + wm * 32 + mt * 16 + (lane >> 2) + hf * 8;
                float* crow = &Cout[(size_t)r * CC];
                #pragma unroll
                for (int nt = 0; nt < 8; nt++) {
                    int cc = colbase + nt * 8 + (lane & 3) * 2;
                    float2 o;
                    o.x = acc[mt][nt][hf * 2 + 0] + bias[cc];
                    o.y = acc[mt][nt][hf * 2 + 1] + bias[cc + 1];
                    *(float2*)&crow[cc] = o;
                }
            }
        }
    }
}

// ---------------------------------------------------------------------------
// Flash attention, fp16 HMMA. Per CTA: 128 q-rows of one (b,h); 8 warps,
// warp = 16 q-rows x 64 keys per block. Q pre-scaled by 1/sqrt(d).
// Epilogue writes bf16 hi/hi/lo split directly into Abuf (out-proj input).
// ---------------------------------------------------------------------------
#define FL_SMEM (49152 + 128)

__global__ __launch_bounds__(256, 1) void flash_mma_kernel(
    const __half* __restrict__ Qh, const __half* __restrict__ Kh,
    const __half* __restrict__ Vh, __nv_bfloat16* __restrict__ Abuf)
{
    extern __shared__ char smraw[];
    char* smp = (char*)(((uintptr_t)smraw + 127) & ~(uintptr_t)127);
    const uint32_t sb = smem_u32(smp);
    const uint32_t sQ = 0, sK[2] = {16384u, 24576u}, sV[2] = {32768u, 40960u};

    const int tid = threadIdx.x;
    const int lane = tid & 31, w = tid >> 5;
    const int bh = blockIdx.y;
    const int q0 = blockIdx.x * 128;
    const size_t base = (size_t)bh * NSEQ * DD;

    // Q tile 128x64 fp16, once (plain vector loads)
    {
        const char* gQ = (const char*)(Qh + base + (size_t)q0 * DD);
        #pragma unroll
        for (int i = 0; i < 4; i++) {
            int idx = tid + i * 256;
            int r = idx >> 3, c = (idx & 7) * 16;
            *(uint4*)(smp + sQ + SW128(r * 128 + c)) =
                *(const uint4*)(gQ + (size_t)r * 128 + c);
        }
    }

    const char* gK = (const char*)(Kh + base);
    const char* gV = (const char*)(Vh + base);
    const int crow = tid >> 3;          // 0..31
    const int ccol = (tid & 7) * 16;

    auto load_kv = [&](int kc, int buf) {
        const size_t rb = (size_t)kc * 64 * 128;
        #pragma unroll
        for (int i = 0; i < 2; i++) {
            int r = crow + i * 32;
            CP16(sb + sK[buf] + SW128(r * 128 + ccol), gK + rb + (size_t)r * 128 + ccol);
        }
        #pragma unroll
        for (int i = 0; i < 2; i++) {
            int r = crow + i * 32;
            CP16(sb + sV[buf] + SW128(r * 128 + ccol), gV + rb + (size_t)r * 128 + ccol);
        }
    };

    load_kv(0, 0);
    CP_COMMIT();

    float oacc[8][4];
    #pragma unroll
    for (int nt = 0; nt < 8; nt++)
        #pragma unroll
        for (int j = 0; j < 4; j++) oacc[nt][j] = 0.f;
    float m0r = -1e30f, m1r = -1e30f, l0r = 0.f, l1r = 0.f;

    for (int kc = 0; kc < NSEQ / 64; kc++) {
        CP_WAIT0();
        __syncthreads();
        if (kc + 1 < NSEQ / 64) {
            load_kv(kc + 1, (kc + 1) & 1);
            CP_COMMIT();
        }
        const int buf = kc & 1;

        // ---- S = Q @ K^T (pre-scaled) ----
        float sacc[8][4];
        #pragma unroll
        for (int nt = 0; nt < 8; nt++)
            #pragma unroll
            for (int j = 0; j < 4; j++) sacc[nt][j] = 0.f;

        #pragma unroll
        for (int ks = 0; ks < 4; ks++) {
            uint32_t a[4];
            ldsm4(a[0], a[1], a[2], a[3],
                  sb + sQ + SW128((w * 16 + (lane & 15)) * 128 +
                                  ks * 32 + ((lane >> 4) << 4)));
            #pragma unroll
            for (int p = 0; p < 4; p++) {
                uint32_t b0, b1, b2, b3;
                ldsm4(b0, b1, b2, b3,
                      sb + sK[buf] + SW128((p * 16 + (lane & 7) + ((lane >> 4) & 1) * 8) * 128 +
                                           ks * 32 + ((lane >> 3) & 1) * 16));
                mma_f16(sacc[2 * p], a, b0, b1);
                mma_f16(sacc[2 * p + 1], a, b2, b3);
            }
        }

        // ---- online softmax (rows: lane>>2 and +8) ----
        float mx0 = m0r, mx1 = m1r;
        #pragma unroll
        for (int nt = 0; nt < 8; nt++) {
            mx0 = fmaxf(mx0, fmaxf(sacc[nt][0], sacc[nt][1]));
            mx1 = fmaxf(mx1, fmaxf(sacc[nt][2], sacc[nt][3]));
        }
        mx0 = fmaxf(mx0, __shfl_xor_sync(0xffffffffu, mx0, 1));
        mx0 = fmaxf(mx0, __shfl_xor_sync(0xffffffffu, mx0, 2));
        mx1 = fmaxf(mx1, __shfl_xor_sync(0xffffffffu, mx1, 1));
        mx1 = fmaxf(mx1, __shfl_xor_sync(0xffffffffu, mx1, 2));

        float alpha0 = __expf(m0r - mx0);
        float alpha1 = __expf(m1r - mx1);
        m0r = mx0; m1r = mx1;

        float rs0 = 0.f, rs1 = 0.f;
        #pragma unroll
        for (int nt = 0; nt < 8; nt++) {
            sacc[nt][0] = __expf(sacc[nt][0] - mx0);
            sacc[nt][1] = __expf(sacc[nt][1] - mx0);
            sacc[nt][2] = __expf(sacc[nt][2] - mx1);
            sacc[nt][3] = __expf(sacc[nt][3] - mx1);
            rs0 += sacc[nt][0] + sacc[nt][1];
            rs1 += sacc[nt][2] + sacc[nt][3];
        }
        rs0 += __shfl_xor_sync(0xffffffffu, rs0, 1);
        rs0 += __shfl_xor_sync(0xffffffffu, rs0, 2);
        rs1 += __shfl_xor_sync(0xffffffffu, rs1, 1);
        rs1 += __shfl_xor_sync(0xffffffffu, rs1, 2);
        l0r = l0r * alpha0 + rs0;
        l1r = l1r * alpha1 + rs1;

        #pragma unroll
        for (int nt = 0; nt < 8; nt++) {
            oacc[nt][0] *= alpha0; oacc[nt][1] *= alpha0;
            oacc[nt][2] *= alpha1; oacc[nt][3] *= alpha1;
        }

        // ---- O += P @ V ----
        #pragma unroll
        for (int kt = 0; kt < 4; kt++) {
            uint32_t pa[4];
            pa[0] = pack_h2(sacc[2 * kt][0],     sacc[2 * kt][1]);
            pa[1] = pack_h2(sacc[2 * kt][2],     sacc[2 * kt][3]);
            pa[2] = pack_h2(sacc[2 * kt + 1][0], sacc[2 * kt + 1][1]);
            pa[3] = pack_h2(sacc[2 * kt + 1][2], sacc[2 * kt + 1][3]);
            #pragma unroll
            for (int nt = 0; nt < 8; nt++) {
                uint32_t v0, v1;
                ldsm2t(v0, v1,
                       sb + sV[buf] + SW128((kt * 16 + (lane & 15)) * 128 + nt * 16));
                mma_f16(oacc[nt], pa, v0, v1);
            }
        }
        __syncthreads();
    }

    // ---- epilogue: write bf16 hi|hi|lo split directly into Abuf ----
    const float inv0 = 1.f / l0r, inv1 = 1.f / l1r;
    const int b = bh >> 4, h = bh & 15;
    #pragma unroll
    for (int hf = 0; hf < 2; hf++) {
        int n = q0 + w * 16 + (lane >> 2) + hf * 8;
        float inv = hf ? inv1 : inv0;
        __nv_bfloat16* arow = Abuf + ((size_t)b * NSEQ + n) * GK;
        #pragma unroll
        for (int nt = 0; nt < 8; nt++) {
            int col = h * 64 + nt * 8 + (lane & 3) * 2;
            float o0 = oacc[nt][hf * 2 + 0] * inv;
            float o1 = oacc[nt][hf * 2 + 1] * inv;
            __nv_bfloat16 h0 = __float2bfloat16_rn(o0);
            __nv_bfloat16 h1 = __float2bfloat16_rn(o1);
            __nv_bfloat162 hi2; hi2.x = h0; hi2.y = h1;
            __nv_bfloat162 lo2;
            lo2.x = __float2bfloat16_rn(o0 - __bfloat162float(h0));
            lo2.y = __float2bfloat16_rn(o1 - __bfloat162float(h1));
            *(__nv_bfloat162*)&arow[col]        = hi2;
            *(__nv_bfloat162*)&arow[col + 1024] = hi2;
            *(__nv_bfloat162*)&arow[col + 2048] = lo2;
        }
    }
}

// ---------------------------------------------------------------------------
// Launcher
// ---------------------------------------------------------------------------
extern "C" void kernel_launch(void* const* d_in, const int* in_sizes, int n_in,
                              void* d_out, int out_size)
{
    const float* x     = (const float*)d_in[0];
    const float* W_qkv = (const float*)d_in[1];
    const float* b_qkv = (const float*)d_in[2];
    const float* W_out = (const float*)d_in[3];
    const float* b_out = (const float*)d_in[4];
    float* out = (float*)d_out;

    __half *qh, *kh, *vh;
    __nv_bfloat16 *Abuf, *Bq, *Bo;
    cudaGetSymbolAddress((void**)&qh,   g_qh);
    cudaGetSymbolAddress((void**)&kh,   g_kh);
    cudaGetSymbolAddress((void**)&vh,   g_vh);
    cudaGetSymbolAddress((void**)&Abuf, g_Abuf);
    cudaGetSymbolAddress((void**)&Bq,   g_Bq);
    cudaGetSymbolAddress((void**)&Bo,   g_Bo);

    cudaFuncSetAttribute(mma_gemm_kernel<0>,
                         cudaFuncAttributeMaxDynamicSharedMemorySize, GEMM_SMEM);
    cudaFuncSetAttribute(mma_gemm_kernel<1>,
                         cudaFuncAttributeMaxDynamicSharedMemorySize, GEMM_SMEM);
    cudaFuncSetAttribute(flash_mma_kernel,
                         cudaFuncAttributeMaxDynamicSharedMemorySize, FL_SMEM);

    // 1) split x -> A' (hi|hi|lo)
    split_x_kernel<<<MM * 512 / 256, 256>>>(x, Abuf);
    // 2) split+transpose weights -> K-major bf16 [hi;lo;hi]
    {
        dim3 blk(32, 8);
        transw_kernel<<<dim3(CC / 32, K3 / 32), blk>>>(W_qkv, Bq, CC, K3);
        transw_kernel<<<dim3(CC / 32, CC / 32), blk>>>(W_out, Bo, CC, CC);
    }
    // 3) QKV projection (HMMA bf16x3) -> fp16 Q(scaled)/K/V
    mma_gemm_kernel<0><<<dim3(K3 / 128, MM / 128), 256, GEMM_SMEM>>>(
        Abuf, Bq, b_qkv, nullptr, qh, kh, vh);
    // 4) Flash attention (fp16 HMMA) -> Abuf (bf16x3 split, fused)
    flash_mma_kernel<<<dim3(NSEQ / 128, BB * HH), 256, FL_SMEM>>>(qh, kh, vh, Abuf);
    // 5) Output projection (HMMA bf16x3) -> out
    mma_gemm_kernel<1><<<dim3(CC / 128, MM / 128), 256, GEMM_SMEM>>>(
        Abuf, Bo, b_out, out, nullptr, nullptr, nullptr);
}

// round 4
// speedup vs baseline: 5.4756x; 1.5073x over previous
#include <cuda_runtime.h>
#include <cuda_fp16.h>
#include <math.h>
#include <stdint.h>

#define BB 2
#define HH 16
#define NSEQ 2048
#define DD 64
#define CC 1024
#define MM (BB*NSEQ)      /* 4096 */
#define K3 (3*CC)         /* 3072 */
#define GK2 2048          /* K' = 2*1024 for fp16x2 split */

// ---------------------------------------------------------------------------
// Scratch (__device__ globals; allocation-free rule)
// ---------------------------------------------------------------------------
__device__ __align__(256) __half g_qh[(size_t)BB*HH*NSEQ*DD];   // Q fp16, pre-scaled 0.125
__device__ __align__(256) __half g_kh[(size_t)BB*HH*NSEQ*DD];
__device__ __align__(256) __half g_vh[(size_t)BB*HH*NSEQ*DD];
__device__ __align__(256) __half g_Abuf[(size_t)MM*GK2];        // A' = [hi | lo]
__device__ __align__(256) __half g_Bq[(size_t)K3*GK2];          // W_qkv' rows n: [hi ; hi]
__device__ __align__(256) __half g_Bo[(size_t)CC*GK2];          // W_out'

// ---------------------------------------------------------------------------
// PTX helpers (baseline sm_80 ISA — safe on plain sm_103 target)
// ---------------------------------------------------------------------------
__device__ __forceinline__ uint32_t smem_u32(const void* p) {
    uint32_t a;
    asm("{ .reg .u64 t; cvta.to.shared.u64 t, %1; cvt.u32.u64 %0, t; }"
        : "=r"(a) : "l"(p));
    return a;
}

#define SW128(off) ((off) ^ (((off) >> 3) & 0x70))

#define CP16(dst, src) \
    asm volatile("cp.async.cg.shared.global [%0], [%1], 16;" :: "r"(dst), "l"(src))
#define CP_COMMIT() asm volatile("cp.async.commit_group;" ::: "memory")
#define CP_WAIT0()  asm volatile("cp.async.wait_group 0;" ::: "memory")
#define CP_WAIT1()  asm volatile("cp.async.wait_group 1;" ::: "memory")

__device__ __forceinline__ void ldsm4(uint32_t& r0, uint32_t& r1,
                                      uint32_t& r2, uint32_t& r3, uint32_t a) {
    asm volatile("ldmatrix.sync.aligned.m8n8.x4.shared.b16 {%0,%1,%2,%3}, [%4];"
        : "=r"(r0), "=r"(r1), "=r"(r2), "=r"(r3) : "r"(a));
}
__device__ __forceinline__ void ldsm2t(uint32_t& r0, uint32_t& r1, uint32_t a) {
    asm volatile("ldmatrix.sync.aligned.m8n8.x2.trans.shared.b16 {%0,%1}, [%2];"
        : "=r"(r0), "=r"(r1) : "r"(a));
}
__device__ __forceinline__ void mma_f16(float* c, const uint32_t* a, uint32_t b0, uint32_t b1) {
    asm volatile("mma.sync.aligned.m16n8k16.row.col.f32.f16.f16.f32 "
        "{%0,%1,%2,%3}, {%4,%5,%6,%7}, {%8,%9}, {%0,%1,%2,%3};"
        : "+f"(c[0]), "+f"(c[1]), "+f"(c[2]), "+f"(c[3])
        : "r"(a[0]), "r"(a[1]), "r"(a[2]), "r"(a[3]), "r"(b0), "r"(b1));
}

__device__ __forceinline__ uint32_t pack_h2(float lo, float hi) {
    __half2 h = __float22half2_rn(make_float2(lo, hi));
    return *(uint32_t*)&h;
}

// ---------------------------------------------------------------------------
// Prep: split fp32 [M][1024] -> fp16 [M][2048] = [hi | lo]
// ---------------------------------------------------------------------------
__global__ __launch_bounds__(256) void split_x_kernel(
    const float* __restrict__ in, __half* __restrict__ out)
{
    int idx = blockIdx.x * 256 + threadIdx.x;   // one per 2 floats; grid exact
    int row = idx >> 9;
    int c2 = (idx & 511) * 2;
    float2 v = *(const float2*)&in[(size_t)row * 1024 + c2];
    __half2 hi = __float22half2_rn(v);
    float2 r = make_float2(v.x - __half2float(hi.x), v.y - __half2float(hi.y));
    __half2 lo = __float22half2_rn(r);
    __half2* o = (__half2*)(out + (size_t)row * GK2);
    int p = c2 >> 1;
    o[p]       = hi;
    o[512 + p] = lo;
}

// ---------------------------------------------------------------------------
// Prep: W [1024][N] fp32 -> B' [N][2048] fp16 K-major, [hi ; hi] (duplicated)
// ---------------------------------------------------------------------------
__global__ void transw_kernel(const float* __restrict__ W,
                              __half* __restrict__ Bo, int N)
{
    __shared__ float t[32][33];
    int k0 = blockIdx.x * 32, n0 = blockIdx.y * 32;
    int tx = threadIdx.x, ty = threadIdx.y;   // (32, 8)
    #pragma unroll
    for (int i = 0; i < 4; i++)
        t[ty + i * 8][tx] = W[(size_t)(k0 + ty + i * 8) * N + n0 + tx];
    __syncthreads();
    #pragma unroll
    for (int i = 0; i < 4; i++) {
        int n = n0 + ty + i * 8, k = k0 + tx;
        __half h = __float2half_rn(t[tx][ty + i * 8]);
        __half* row = Bo + (size_t)n * GK2;
        row[k]        = h;
        row[1024 + k] = h;
    }
}

// ---------------------------------------------------------------------------
// HMMA GEMM: D[M][N] = A'[M][GK2] @ B'[N][GK2]^T (+bias)
// BM=128, BN=128, BK=64, 3-stage cp.async, 1 sync/iter, 2 CTAs/SM.
// 8 warps: 4(m) x 2(n) -> warp tile 32x64.
// MODE 0: qkv — fp16 to g_qh/g_kh/g_vh in [b,h,n,d], Q pre-scaled 0.125.
// MODE 1: out proj — fp32 + bias to Cout.
// ---------------------------------------------------------------------------
#define STAGE_BYTES 32768
#define GEMM_SMEM (3 * STAGE_BYTES + 128)
#define KITERS (GK2 / 64)

template<int MODE>
__global__ __launch_bounds__(256, 2) void mma_gemm_kernel(
    const __half* __restrict__ A,
    const __half* __restrict__ Bm,
    const float* __restrict__ bias,
    float* __restrict__ Cout,
    __half* __restrict__ Qh, __half* __restrict__ Kh, __half* __restrict__ Vh)
{
    extern __shared__ char smraw[];
    char* smp = (char*)(((uintptr_t)smraw + 127) & ~(uintptr_t)127);
    const uint32_t sb = smem_u32(smp);

    const int tid = threadIdx.x;
    const int lane = tid & 31, wid = tid >> 5;
    const int wm = wid & 3, wn = wid >> 2;
    const int m0 = blockIdx.y * 128;
    const int n0 = blockIdx.x * 128;

    const char* gA = (const char*)A + (size_t)m0 * (GK2 * 2);
    const char* gB = (const char*)Bm + (size_t)n0 * (GK2 * 2);

    const int crow = tid >> 3;           // 0..31, +32 per i
    const int ccol = (tid & 7) * 16;

    auto load_tile = [&](int it, int buf) {
        const uint32_t ao = (uint32_t)buf * STAGE_BYTES;
        const uint32_t bo = ao + 16384u;
        const size_t kbyte = (size_t)it * 128;
        #pragma unroll
        for (int i = 0; i < 4; i++) {
            int r = crow + i * 32;
            CP16(sb + ao + SW128(r * 128 + ccol),
                 gA + (size_t)r * (GK2 * 2) + kbyte + ccol);
        }
        #pragma unroll
        for (int i = 0; i < 4; i++) {
            int r = crow + i * 32;
            CP16(sb + bo + SW128(r * 128 + ccol),
                 gB + (size_t)r * (GK2 * 2) + kbyte + ccol);
        }
    };

    float acc[2][8][4];
    #pragma unroll
    for (int mt = 0; mt < 2; mt++)
        #pragma unroll
        for (int nt = 0; nt < 8; nt++)
            #pragma unroll
            for (int j = 0; j < 4; j++) acc[mt][nt][j] = 0.f;

    load_tile(0, 0); CP_COMMIT();
    load_tile(1, 1); CP_COMMIT();

    int buf = 0;
    for (int it = 0; it < KITERS; it++) {
        CP_WAIT1();
        __syncthreads();
        if (it + 2 < KITERS) load_tile(it + 2, (buf + 2) % 3);
        CP_COMMIT();   // unconditional (possibly empty) keeps wait_group 1 uniform

        const uint32_t ao = (uint32_t)buf * STAGE_BYTES;
        const uint32_t bo = ao + 16384u;

        #pragma unroll
        for (int ks = 0; ks < 4; ks++) {
            uint32_t a[2][4];
            #pragma unroll
            for (int mt = 0; mt < 2; mt++) {
                uint32_t addr = sb + ao +
                    SW128((wm * 32 + mt * 16 + (lane & 15)) * 128 +
                          ks * 32 + ((lane >> 4) << 4));
                ldsm4(a[mt][0], a[mt][1], a[mt][2], a[mt][3], addr);
            }
            uint32_t b[8][2];
            #pragma unroll
            for (int p = 0; p < 4; p++) {
                uint32_t addr = sb + bo +
                    SW128((wn * 64 + p * 16 + (lane & 7) + ((lane >> 4) & 1) * 8) * 128 +
                          ks * 32 + ((lane >> 3) & 1) * 16);
                ldsm4(b[2 * p][0], b[2 * p][1], b[2 * p + 1][0], b[2 * p + 1][1], addr);
            }
            #pragma unroll
            for (int mt = 0; mt < 2; mt++)
                #pragma unroll
                for (int nt = 0; nt < 8; nt++)
                    mma_f16(acc[mt][nt], a[mt], b[nt][0], b[nt][1]);
        }
        buf = (buf + 1) % 3;
    }

    // ---------------- epilogue ----------------
    const int colbase = n0 + wn * 64;    // 64-aligned -> single head per warp
    if (MODE == 0) {
        const int s = colbase >> 10;
        const int h = (colbase >> 6) & 15;
        __half* dst = (s == 0) ? Qh : ((s == 1) ? Kh : Vh);
        const float scl = (s == 0) ? 0.125f : 1.0f;
        #pragma unroll
        for (int mt = 0; mt < 2; mt++) {
            #pragma unroll
            for (int hf = 0; hf < 2; hf++) {
                int r = m0 + wm * 32 + mt * 16 + (lane >> 2) + hf * 8;
                int bidx = r >> 11, n = r & (NSEQ - 1);
                size_t rowoff = (((size_t)bidx * HH + h) * NSEQ + n) * DD;
                #pragma unroll
                for (int nt = 0; nt < 8; nt++) {
                    int dd = nt * 8 + (lane & 3) * 2;
                    float v0 = (acc[mt][nt][hf * 2 + 0] + bias[colbase + dd]) * scl;
                    float v1 = (acc[mt][nt][hf * 2 + 1] + bias[colbase + dd + 1]) * scl;
                    *(__half2*)&dst[rowoff + dd] =
                        __float22half2_rn(make_float2(v0, v1));
                }
            }
        }
    } else {
        #pragma unroll
        for (int mt = 0; mt < 2; mt++) {
            #pragma unroll
            for (int hf = 0; hf < 2; hf++) {
                int r = m0 + wm * 32 + mt * 16 + (lane >> 2) + hf * 8;
                float* crow = &Cout[(size_t)r * CC];
                #pragma unroll
                for (int nt = 0; nt < 8; nt++) {
                    int cc = colbase + nt * 8 + (lane & 3) * 2;
                    float2 o;
                    o.x = acc[mt][nt][hf * 2 + 0] + bias[cc];
                    o.y = acc[mt][nt][hf * 2 + 1] + bias[cc + 1];
                    *(float2*)&crow[cc] = o;
                }
            }
        }
    }
}

// ---------------------------------------------------------------------------
// Flash attention, fp16 HMMA. Per CTA: 128 q-rows of one (b,h); 8 warps,
// warp = 16 q-rows x 64 keys per block. Q pre-scaled by 1/sqrt(d).
// Epilogue writes fp16 [hi|lo] split directly into Abuf (out-proj input).
// ---------------------------------------------------------------------------
#define FL_SMEM (49152 + 128)

__global__ __launch_bounds__(256, 1) void flash_mma_kernel(
    const __half* __restrict__ Qh, const __half* __restrict__ Kh,
    const __half* __restrict__ Vh, __half* __restrict__ Abuf)
{
    extern __shared__ char smraw[];
    char* smp = (char*)(((uintptr_t)smraw + 127) & ~(uintptr_t)127);
    const uint32_t sb = smem_u32(smp);
    const uint32_t sQ = 0, sK[2] = {16384u, 24576u}, sV[2] = {32768u, 40960u};

    const int tid = threadIdx.x;
    const int lane = tid & 31, w = tid >> 5;
    const int bh = blockIdx.y;
    const int q0 = blockIdx.x * 128;
    const size_t base = (size_t)bh * NSEQ * DD;

    // Q tile 128x64 fp16, once
    {
        const char* gQ = (const char*)(Qh + base + (size_t)q0 * DD);
        #pragma unroll
        for (int i = 0; i < 4; i++) {
            int idx = tid + i * 256;
            int r = idx >> 3, c = (idx & 7) * 16;
            *(uint4*)(smp + sQ + SW128(r * 128 + c)) =
                *(const uint4*)(gQ + (size_t)r * 128 + c);
        }
    }

    const char* gK = (const char*)(Kh + base);
    const char* gV = (const char*)(Vh + base);
    const int crow = tid >> 3;
    const int ccol = (tid & 7) * 16;

    auto load_kv = [&](int kc, int buf) {
        const size_t rb = (size_t)kc * 64 * 128;
        #pragma unroll
        for (int i = 0; i < 2; i++) {
            int r = crow + i * 32;
            CP16(sb + sK[buf] + SW128(r * 128 + ccol), gK + rb + (size_t)r * 128 + ccol);
        }
        #pragma unroll
        for (int i = 0; i < 2; i++) {
            int r = crow + i * 32;
            CP16(sb + sV[buf] + SW128(r * 128 + ccol), gV + rb + (size_t)r * 128 + ccol);
        }
    };

    load_kv(0, 0);
    CP_COMMIT();

    float oacc[8][4];
    #pragma unroll
    for (int nt = 0; nt < 8; nt++)
        #pragma unroll
        for (int j = 0; j < 4; j++) oacc[nt][j] = 0.f;
    float m0r = -1e30f, m1r = -1e30f, l0r = 0.f, l1r = 0.f;

    for (int kc = 0; kc < NSEQ / 64; kc++) {
        CP_WAIT0();
        __syncthreads();
        if (kc + 1 < NSEQ / 64) {
            load_kv(kc + 1, (kc + 1) & 1);
            CP_COMMIT();
        }
        const int buf = kc & 1;

        // ---- S = Q @ K^T (pre-scaled) ----
        float sacc[8][4];
        #pragma unroll
        for (int nt = 0; nt < 8; nt++)
            #pragma unroll
            for (int j = 0; j < 4; j++) sacc[nt][j] = 0.f;

        #pragma unroll
        for (int ks = 0; ks < 4; ks++) {
            uint32_t a[4];
            ldsm4(a[0], a[1], a[2], a[3],
                  sb + sQ + SW128((w * 16 + (lane & 15)) * 128 +
                                  ks * 32 + ((lane >> 4) << 4)));
            #pragma unroll
            for (int p = 0; p < 4; p++) {
                uint32_t b0, b1, b2, b3;
                ldsm4(b0, b1, b2, b3,
                      sb + sK[buf] + SW128((p * 16 + (lane & 7) + ((lane >> 4) & 1) * 8) * 128 +
                                           ks * 32 + ((lane >> 3) & 1) * 16));
                mma_f16(sacc[2 * p], a, b0, b1);
                mma_f16(sacc[2 * p + 1], a, b2, b3);
            }
        }

        // ---- online softmax ----
        float mx0 = m0r, mx1 = m1r;
        #pragma unroll
        for (int nt = 0; nt < 8; nt++) {
            mx0 = fmaxf(mx0, fmaxf(sacc[nt][0], sacc[nt][1]));
            mx1 = fmaxf(mx1, fmaxf(sacc[nt][2], sacc[nt][3]));
        }
        mx0 = fmaxf(mx0, __shfl_xor_sync(0xffffffffu, mx0, 1));
        mx0 = fmaxf(mx0, __shfl_xor_sync(0xffffffffu, mx0, 2));
        mx1 = fmaxf(mx1, __shfl_xor_sync(0xffffffffu, mx1, 1));
        mx1 = fmaxf(mx1, __shfl_xor_sync(0xffffffffu, mx1, 2));

        float alpha0 = __expf(m0r - mx0);
        float alpha1 = __expf(m1r - mx1);
        m0r = mx0; m1r = mx1;

        float rs0 = 0.f, rs1 = 0.f;
        #pragma unroll
        for (int nt = 0; nt < 8; nt++) {
            sacc[nt][0] = __expf(sacc[nt][0] - mx0);
            sacc[nt][1] = __expf(sacc[nt][1] - mx0);
            sacc[nt][2] = __expf(sacc[nt][2] - mx1);
            sacc[nt][3] = __expf(sacc[nt][3] - mx1);
            rs0 += sacc[nt][0] + sacc[nt][1];
            rs1 += sacc[nt][2] + sacc[nt][3];
        }
        rs0 += __shfl_xor_sync(0xffffffffu, rs0, 1);
        rs0 += __shfl_xor_sync(0xffffffffu, rs0, 2);
        rs1 += __shfl_xor_sync(0xffffffffu, rs1, 1);
        rs1 += __shfl_xor_sync(0xffffffffu, rs1, 2);
        l0r = l0r * alpha0 + rs0;
        l1r = l1r * alpha1 + rs1;

        #pragma unroll
        for (int nt = 0; nt < 8; nt++) {
            oacc[nt][0] *= alpha0; oacc[nt][1] *= alpha0;
            oacc[nt][2] *= alpha1; oacc[nt][3] *= alpha1;
        }

        // ---- O += P @ V ----
        #pragma unroll
        for (int kt = 0; kt < 4; kt++) {
            uint32_t pa[4];
            pa[0] = pack_h2(sacc[2 * kt][0],     sacc[2 * kt][1]);
            pa[1] = pack_h2(sacc[2 * kt][2],     sacc[2 * kt][3]);
            pa[2] = pack_h2(sacc[2 * kt + 1][0], sacc[2 * kt + 1][1]);
            pa[3] = pack_h2(sacc[2 * kt + 1][2], sacc[2 * kt + 1][3]);
            #pragma unroll
            for (int nt = 0; nt < 8; nt++) {
                uint32_t v0, v1;
                ldsm2t(v0, v1,
                       sb + sV[buf] + SW128((kt * 16 + (lane & 15)) * 128 + nt * 16));
                mma_f16(oacc[nt], pa, v0, v1);
            }
        }
        __syncthreads();
    }

    // ---- epilogue: fp16 [hi | lo] split into Abuf ----
    const float inv0 = 1.f / l0r, inv1 = 1.f / l1r;
    const int b = bh >> 4, h = bh & 15;
    #pragma unroll
    for (int hf = 0; hf < 2; hf++) {
        int n = q0 + w * 16 + (lane >> 2) + hf * 8;
        float inv = hf ? inv1 : inv0;
        __half* arow = Abuf + ((size_t)b * NSEQ + n) * GK2;
        #pragma unroll
        for (int nt = 0; nt < 8; nt++) {
            int col = h * 64 + nt * 8 + (lane & 3) * 2;
            float o0 = oacc[nt][hf * 2 + 0] * inv;
            float o1 = oacc[nt][hf * 2 + 1] * inv;
            __half2 hi = __float22half2_rn(make_float2(o0, o1));
            __half2 lo = __float22half2_rn(make_float2(
                o0 - __half2float(hi.x), o1 - __half2float(hi.y)));
            *(__half2*)&arow[col]        = hi;
            *(__half2*)&arow[col + 1024] = lo;
        }
    }
}

// ---------------------------------------------------------------------------
// Launcher
// ---------------------------------------------------------------------------
extern "C" void kernel_launch(void* const* d_in, const int* in_sizes, int n_in,
                              void* d_out, int out_size)
{
    const float* x     = (const float*)d_in[0];
    const float* W_qkv = (const float*)d_in[1];
    const float* b_qkv = (const float*)d_in[2];
    const float* W_out = (const float*)d_in[3];
    const float* b_out = (const float*)d_in[4];
    float* out = (float*)d_out;

    __half *qh, *kh, *vh, *Abuf, *Bq, *Bo;
    cudaGetSymbolAddress((void**)&qh,   g_qh);
    cudaGetSymbolAddress((void**)&kh,   g_kh);
    cudaGetSymbolAddress((void**)&vh,   g_vh);
    cudaGetSymbolAddress((void**)&Abuf, g_Abuf);
    cudaGetSymbolAddress((void**)&Bq,   g_Bq);
    cudaGetSymbolAddress((void**)&Bo,   g_Bo);

    cudaFuncSetAttribute(mma_gemm_kernel<0>,
                         cudaFuncAttributeMaxDynamicSharedMemorySize, GEMM_SMEM);
    cudaFuncSetAttribute(mma_gemm_kernel<1>,
                         cudaFuncAttributeMaxDynamicSharedMemorySize, GEMM_SMEM);
    cudaFuncSetAttribute(flash_mma_kernel,
                         cudaFuncAttributeMaxDynamicSharedMemorySize, FL_SMEM);

    // 1) split x -> A' [hi|lo] fp16
    split_x_kernel<<<MM * 512 / 256, 256>>>(x, Abuf);
    // 2) transpose weights -> K-major fp16 [hi;hi]
    {
        dim3 blk(32, 8);
        transw_kernel<<<dim3(CC / 32, K3 / 32), blk>>>(W_qkv, Bq, K3);
        transw_kernel<<<dim3(CC / 32, CC / 32), blk>>>(W_out, Bo, CC);
    }
    // 3) QKV projection (HMMA fp16x2) -> fp16 Q(scaled)/K/V
    mma_gemm_kernel<0><<<dim3(K3 / 128, MM / 128), 256, GEMM_SMEM>>>(
        Abuf, Bq, b_qkv, nullptr, qh, kh, vh);
    // 4) Flash attention (fp16 HMMA) -> Abuf (fp16x2 split, fused)
    flash_mma_kernel<<<dim3(NSEQ / 128, BB * HH), 256, FL_SMEM>>>(qh, kh, vh, Abuf);
    // 5) Output projection (HMMA fp16x2) -> out
    mma_gemm_kernel<1><<<dim3(CC / 128, MM / 128), 256, GEMM_SMEM>>>(
        Abuf, Bo, b_out, out, nullptr, nullptr, nullptr);
}

// round 5
// speedup vs baseline: 6.2076x; 1.1337x over previous
#include <cuda_runtime.h>
#include <cuda_fp16.h>
#include <math.h>
#include <stdint.h>

#define BB 2
#define HH 16
#define NSEQ 2048
#define DD 64
#define CC 1024
#define MM (BB*NSEQ)      /* 4096 */
#define K3 (3*CC)         /* 3072 */
#define GK2 2048          /* K' = 2*1024 for fp16x2 split (qkv proj only) */

// ---------------------------------------------------------------------------
// Scratch (__device__ globals; allocation-free rule)
// ---------------------------------------------------------------------------
__device__ __align__(256) __half g_qh[(size_t)BB*HH*NSEQ*DD];   // Q fp16, pre-scaled 0.125
__device__ __align__(256) __half g_kh[(size_t)BB*HH*NSEQ*DD];
__device__ __align__(256) __half g_vh[(size_t)BB*HH*NSEQ*DD];
__device__ __align__(256) __half g_Abuf[(size_t)MM*GK2];        // x' = [hi | lo]
__device__ __align__(256) __half g_Oh[(size_t)MM*CC];           // attention out, fp16
__device__ __align__(256) __half g_Bq[(size_t)K3*GK2];          // W_qkv' rows n: [hi ; hi]
__device__ __align__(256) __half g_Bo[(size_t)CC*CC];           // W_out fp16 K-major

// ---------------------------------------------------------------------------
// PTX helpers (baseline sm_80 ISA — safe on plain sm_103 target)
// ---------------------------------------------------------------------------
__device__ __forceinline__ uint32_t smem_u32(const void* p) {
    uint32_t a;
    asm("{ .reg .u64 t; cvta.to.shared.u64 t, %1; cvt.u32.u64 %0, t; }"
        : "=r"(a) : "l"(p));
    return a;
}

#define SW128(off) ((off) ^ (((off) >> 3) & 0x70))

#define CP16(dst, src) \
    asm volatile("cp.async.cg.shared.global [%0], [%1], 16;" :: "r"(dst), "l"(src))
#define CP_COMMIT() asm volatile("cp.async.commit_group;" ::: "memory")
#define CP_WAIT0()  asm volatile("cp.async.wait_group 0;" ::: "memory")
#define CP_WAIT1()  asm volatile("cp.async.wait_group 1;" ::: "memory")

__device__ __forceinline__ void ldsm4(uint32_t& r0, uint32_t& r1,
                                      uint32_t& r2, uint32_t& r3, uint32_t a) {
    asm volatile("ldmatrix.sync.aligned.m8n8.x4.shared.b16 {%0,%1,%2,%3}, [%4];"
        : "=r"(r0), "=r"(r1), "=r"(r2), "=r"(r3) : "r"(a));
}
__device__ __forceinline__ void ldsm2t(uint32_t& r0, uint32_t& r1, uint32_t a) {
    asm volatile("ldmatrix.sync.aligned.m8n8.x2.trans.shared.b16 {%0,%1}, [%2];"
        : "=r"(r0), "=r"(r1) : "r"(a));
}
__device__ __forceinline__ void mma_f16(float* c, const uint32_t* a, uint32_t b0, uint32_t b1) {
    asm volatile("mma.sync.aligned.m16n8k16.row.col.f32.f16.f16.f32 "
        "{%0,%1,%2,%3}, {%4,%5,%6,%7}, {%8,%9}, {%0,%1,%2,%3};"
        : "+f"(c[0]), "+f"(c[1]), "+f"(c[2]), "+f"(c[3])
        : "r"(a[0]), "r"(a[1]), "r"(a[2]), "r"(a[3]), "r"(b0), "r"(b1));
}

__device__ __forceinline__ uint32_t pack_h2(float lo, float hi) {
    __half2 h = __float22half2_rn(make_float2(lo, hi));
    return *(uint32_t*)&h;
}

// ---------------------------------------------------------------------------
// Prep: split fp32 [M][1024] -> fp16 [M][2048] = [hi | lo]
// ---------------------------------------------------------------------------
__global__ __launch_bounds__(256) void split_x_kernel(
    const float* __restrict__ in, __half* __restrict__ out)
{
    int idx = blockIdx.x * 256 + threadIdx.x;
    int row = idx >> 9;
    int c2 = (idx & 511) * 2;
    float2 v = *(const float2*)&in[(size_t)row * 1024 + c2];
    __half2 hi = __float22half2_rn(v);
    float2 r = make_float2(v.x - __half2float(hi.x), v.y - __half2float(hi.y));
    __half2 lo = __float22half2_rn(r);
    __half2* o = (__half2*)(out + (size_t)row * GK2);
    int p = c2 >> 1;
    o[p]       = hi;
    o[512 + p] = lo;
}

// ---------------------------------------------------------------------------
// Prep: W [1024][N] fp32 -> B' [N][stride] fp16 K-major; optional duplicate
// of the 1024-wide block at +1024 (for the [hi;hi] qkv layout).
// ---------------------------------------------------------------------------
template<int DUP>
__global__ void transw_kernel(const float* __restrict__ W,
                              __half* __restrict__ Bo, int N, int stride)
{
    __shared__ float t[32][33];
    int k0 = blockIdx.x * 32, n0 = blockIdx.y * 32;
    int tx = threadIdx.x, ty = threadIdx.y;   // (32, 8)
    #pragma unroll
    for (int i = 0; i < 4; i++)
        t[ty + i * 8][tx] = W[(size_t)(k0 + ty + i * 8) * N + n0 + tx];
    __syncthreads();
    #pragma unroll
    for (int i = 0; i < 4; i++) {
        int n = n0 + ty + i * 8, k = k0 + tx;
        __half h = __float2half_rn(t[tx][ty + i * 8]);
        __half* row = Bo + (size_t)n * stride;
        row[k] = h;
        if (DUP) row[1024 + k] = h;
    }
}

// ---------------------------------------------------------------------------
// HMMA GEMM: D[M][N] = A[M][KEXT] @ B[N][KEXT]^T (+bias)
// BM=128, BN=128, BK=64, 3-stage cp.async, 1 sync/iter, 2 CTAs/SM.
// 8 warps: 4(m) x 2(n) -> warp tile 32x64.
// MODE 0: qkv — fp16 to Qh/Kh/Vh in [b,h,n,d], Q pre-scaled 0.125.
// MODE 1: out proj — fp32 + bias to Cout.
// ---------------------------------------------------------------------------
#define STAGE_BYTES 32768
#define GEMM_SMEM (3 * STAGE_BYTES + 128)

template<int MODE, int KEXT>
__global__ __launch_bounds__(256, 2) void mma_gemm_kernel(
    const __half* __restrict__ A,
    const __half* __restrict__ Bm,
    const float* __restrict__ bias,
    float* __restrict__ Cout,
    __half* __restrict__ Qh, __half* __restrict__ Kh, __half* __restrict__ Vh)
{
    constexpr int KITERS = KEXT / 64;
    extern __shared__ char smraw[];
    char* smp = (char*)(((uintptr_t)smraw + 127) & ~(uintptr_t)127);
    const uint32_t sb = smem_u32(smp);

    const int tid = threadIdx.x;
    const int lane = tid & 31, wid = tid >> 5;
    const int wm = wid & 3, wn = wid >> 2;
    const int m0 = blockIdx.y * 128;
    const int n0 = blockIdx.x * 128;

    const char* gA = (const char*)A + (size_t)m0 * (KEXT * 2);
    const char* gB = (const char*)Bm + (size_t)n0 * (KEXT * 2);

    const int crow = tid >> 3;           // 0..31, +32 per i
    const int ccol = (tid & 7) * 16;

    auto load_tile = [&](int it, int buf) {
        const uint32_t ao = (uint32_t)buf * STAGE_BYTES;
        const uint32_t bo = ao + 16384u;
        const size_t kbyte = (size_t)it * 128;
        #pragma unroll
        for (int i = 0; i < 4; i++) {
            int r = crow + i * 32;
            CP16(sb + ao + SW128(r * 128 + ccol),
                 gA + (size_t)r * (KEXT * 2) + kbyte + ccol);
        }
        #pragma unroll
        for (int i = 0; i < 4; i++) {
            int r = crow + i * 32;
            CP16(sb + bo + SW128(r * 128 + ccol),
                 gB + (size_t)r * (KEXT * 2) + kbyte + ccol);
        }
    };

    float acc[2][8][4];
    #pragma unroll
    for (int mt = 0; mt < 2; mt++)
        #pragma unroll
        for (int nt = 0; nt < 8; nt++)
            #pragma unroll
            for (int j = 0; j < 4; j++) acc[mt][nt][j] = 0.f;

    load_tile(0, 0); CP_COMMIT();
    load_tile(1, 1); CP_COMMIT();

    int buf = 0;
    for (int it = 0; it < KITERS; it++) {
        CP_WAIT1();
        __syncthreads();
        if (it + 2 < KITERS) load_tile(it + 2, (buf + 2) % 3);
        CP_COMMIT();   // unconditional keeps wait_group 1 uniform

        const uint32_t ao = (uint32_t)buf * STAGE_BYTES;
        const uint32_t bo = ao + 16384u;

        #pragma unroll
        for (int ks = 0; ks < 4; ks++) {
            uint32_t a[2][4];
            #pragma unroll
            for (int mt = 0; mt < 2; mt++) {
                uint32_t addr = sb + ao +
                    SW128((wm * 32 + mt * 16 + (lane & 15)) * 128 +
                          ks * 32 + ((lane >> 4) << 4));
                ldsm4(a[mt][0], a[mt][1], a[mt][2], a[mt][3], addr);
            }
            uint32_t b[8][2];
            #pragma unroll
            for (int p = 0; p < 4; p++) {
                uint32_t addr = sb + bo +
                    SW128((wn * 64 + p * 16 + (lane & 7) + ((lane >> 4) & 1) * 8) * 128 +
                          ks * 32 + ((lane >> 3) & 1) * 16);
                ldsm4(b[2 * p][0], b[2 * p][1], b[2 * p + 1][0], b[2 * p + 1][1], addr);
            }
            #pragma unroll
            for (int mt = 0; mt < 2; mt++)
                #pragma unroll
                for (int nt = 0; nt < 8; nt++)
                    mma_f16(acc[mt][nt], a[mt], b[nt][0], b[nt][1]);
        }
        buf = (buf + 1) % 3;
    }

    // ---------------- epilogue ----------------
    const int colbase = n0 + wn * 64;    // 64-aligned -> single head per warp
    if (MODE == 0) {
        const int s = colbase >> 10;
        const int h = (colbase >> 6) & 15;
        __half* dst = (s == 0) ? Qh : ((s == 1) ? Kh : Vh);
        const float scl = (s == 0) ? 0.125f : 1.0f;
        #pragma unroll
        for (int mt = 0; mt < 2; mt++) {
            #pragma unroll
            for (int hf = 0; hf < 2; hf++) {
                int r = m0 + wm * 32 + mt * 16 + (lane >> 2) + hf * 8;
                int bidx = r >> 11, n = r & (NSEQ - 1);
                size_t rowoff = (((size_t)bidx * HH + h) * NSEQ + n) * DD;
                #pragma unroll
                for (int nt = 0; nt < 8; nt++) {
                    int dd = nt * 8 + (lane & 3) * 2;
                    float v0 = (acc[mt][nt][hf * 2 + 0] + bias[colbase + dd]) * scl;
                    float v1 = (acc[mt][nt][hf * 2 + 1] + bias[colbase + dd + 1]) * scl;
                    *(__half2*)&dst[rowoff + dd] =
                        __float22half2_rn(make_float2(v0, v1));
                }
            }
        }
    } else {
        #pragma unroll
        for (int mt = 0; mt < 2; mt++) {
            #pragma unroll
            for (int hf = 0; hf < 2; hf++) {
                int r = m0 + wm * 32 + mt * 16 + (lane >> 2) + hf * 8;
                float* crow = &Cout[(size_t)r * CC];
                #pragma unroll
                for (int nt = 0; nt < 8; nt++) {
                    int cc = colbase + nt * 8 + (lane & 3) * 2;
                    float2 o;
                    o.x = acc[mt][nt][hf * 2 + 0] + bias[cc];
                    o.y = acc[mt][nt][hf * 2 + 1] + bias[cc + 1];
                    *(float2*)&crow[cc] = o;
                }
            }
        }
    }
}

// ---------------------------------------------------------------------------
// Flash attention, fp16 HMMA, 2 CTAs/SM. Per CTA: 128 q-rows of one (b,h);
// 8 warps, warp = 16 q-rows. Q pre-scaled by 1/sqrt(d).
// Epilogue writes fp16 O directly into [B,N,C] (out-proj A input).
// ---------------------------------------------------------------------------
#define FL_SMEM (49152 + 128)

__global__ __launch_bounds__(256, 2) void flash_mma_kernel(
    const __half* __restrict__ Qh, const __half* __restrict__ Kh,
    const __half* __restrict__ Vh, __half* __restrict__ Oh)
{
    extern __shared__ char smraw[];
    char* smp = (char*)(((uintptr_t)smraw + 127) & ~(uintptr_t)127);
    const uint32_t sb = smem_u32(smp);
    const uint32_t sQ = 0, sK[2] = {16384u, 24576u}, sV[2] = {32768u, 40960u};

    const int tid = threadIdx.x;
    const int lane = tid & 31, w = tid >> 5;
    const int bh = blockIdx.y;
    const int q0 = blockIdx.x * 128;
    const size_t base = (size_t)bh * NSEQ * DD;

    const char* gK = (const char*)(Kh + base);
    const char* gV = (const char*)(Vh + base);
    const int crow = tid >> 3;
    const int ccol = (tid & 7) * 16;

    // Q tile 128x64 fp16 via cp.async
    {
        const char* gQ = (const char*)(Qh + base + (size_t)q0 * DD);
        #pragma unroll
        for (int i = 0; i < 4; i++) {
            int r = crow + i * 32;
            CP16(sb + sQ + SW128(r * 128 + ccol), gQ + (size_t)r * 128 + ccol);
        }
    }

    auto load_kv = [&](int kc, int buf) {
        const size_t rb = (size_t)kc * 64 * 128;
        #pragma unroll
        for (int i = 0; i < 2; i++) {
            int r = crow + i * 32;
            CP16(sb + sK[buf] + SW128(r * 128 + ccol), gK + rb + (size_t)r * 128 + ccol);
        }
        #pragma unroll
        for (int i = 0; i < 2; i++) {
            int r = crow + i * 32;
            CP16(sb + sV[buf] + SW128(r * 128 + ccol), gV + rb + (size_t)r * 128 + ccol);
        }
    };

    load_kv(0, 0);
    CP_COMMIT();

    float oacc[8][4];
    #pragma unroll
    for (int nt = 0; nt < 8; nt++)
        #pragma unroll
        for (int j = 0; j < 4; j++) oacc[nt][j] = 0.f;
    float m0r = -1e30f, m1r = -1e30f, l0r = 0.f, l1r = 0.f;

    for (int kc = 0; kc < NSEQ / 64; kc++) {
        CP_WAIT0();
        __syncthreads();
        if (kc + 1 < NSEQ / 64) {
            load_kv(kc + 1, (kc + 1) & 1);
            CP_COMMIT();
        }
        const int buf = kc & 1;

        // ---- S = Q @ K^T (pre-scaled) ----
        float sacc[8][4];
        #pragma unroll
        for (int nt = 0; nt < 8; nt++)
            #pragma unroll
            for (int j = 0; j < 4; j++) sacc[nt][j] = 0.f;

        #pragma unroll
        for (int ks = 0; ks < 4; ks++) {
            uint32_t a[4];
            ldsm4(a[0], a[1], a[2], a[3],
                  sb + sQ + SW128((w * 16 + (lane & 15)) * 128 +
                                  ks * 32 + ((lane >> 4) << 4)));
            #pragma unroll
            for (int p = 0; p < 4; p++) {
                uint32_t b0, b1, b2, b3;
                ldsm4(b0, b1, b2, b3,
                      sb + sK[buf] + SW128((p * 16 + (lane & 7) + ((lane >> 4) & 1) * 8) * 128 +
                                           ks * 32 + ((lane >> 3) & 1) * 16));
                mma_f16(sacc[2 * p], a, b0, b1);
                mma_f16(sacc[2 * p + 1], a, b2, b3);
            }
        }

        // ---- online softmax ----
        float mx0 = m0r, mx1 = m1r;
        #pragma unroll
        for (int nt = 0; nt < 8; nt++) {
            mx0 = fmaxf(mx0, fmaxf(sacc[nt][0], sacc[nt][1]));
            mx1 = fmaxf(mx1, fmaxf(sacc[nt][2], sacc[nt][3]));
        }
        mx0 = fmaxf(mx0, __shfl_xor_sync(0xffffffffu, mx0, 1));
        mx0 = fmaxf(mx0, __shfl_xor_sync(0xffffffffu, mx0, 2));
        mx1 = fmaxf(mx1, __shfl_xor_sync(0xffffffffu, mx1, 1));
        mx1 = fmaxf(mx1, __shfl_xor_sync(0xffffffffu, mx1, 2));

        float alpha0 = __expf(m0r - mx0);
        float alpha1 = __expf(m1r - mx1);
        m0r = mx0; m1r = mx1;

        float rs0 = 0.f, rs1 = 0.f;
        #pragma unroll
        for (int nt = 0; nt < 8; nt++) {
            sacc[nt][0] = __expf(sacc[nt][0] - mx0);
            sacc[nt][1] = __expf(sacc[nt][1] - mx0);
            sacc[nt][2] = __expf(sacc[nt][2] - mx1);
            sacc[nt][3] = __expf(sacc[nt][3] - mx1);
            rs0 += sacc[nt][0] + sacc[nt][1];
            rs1 += sacc[nt][2] + sacc[nt][3];
        }
        rs0 += __shfl_xor_sync(0xffffffffu, rs0, 1);
        rs0 += __shfl_xor_sync(0xffffffffu, rs0, 2);
        rs1 += __shfl_xor_sync(0xffffffffu, rs1, 1);
        rs1 += __shfl_xor_sync(0xffffffffu, rs1, 2);
        l0r = l0r * alpha0 + rs0;
        l1r = l1r * alpha1 + rs1;

        #pragma unroll
        for (int nt = 0; nt < 8; nt++) {
            oacc[nt][0] *= alpha0; oacc[nt][1] *= alpha0;
            oacc[nt][2] *= alpha1; oacc[nt][3] *= alpha1;
        }

        // ---- O += P @ V ----
        #pragma unroll
        for (int kt = 0; kt < 4; kt++) {
            uint32_t pa[4];
            pa[0] = pack_h2(sacc[2 * kt][0],     sacc[2 * kt][1]);
            pa[1] = pack_h2(sacc[2 * kt][2],     sacc[2 * kt][3]);
            pa[2] = pack_h2(sacc[2 * kt + 1][0], sacc[2 * kt + 1][1]);
            pa[3] = pack_h2(sacc[2 * kt + 1][2], sacc[2 * kt + 1][3]);
            #pragma unroll
            for (int nt = 0; nt < 8; nt++) {
                uint32_t v0, v1;
                ldsm2t(v0, v1,
                       sb + sV[buf] + SW128((kt * 16 + (lane & 15)) * 128 + nt * 16));
                mma_f16(oacc[nt], pa, v0, v1);
            }
        }
        __syncthreads();
    }

    // ---- epilogue: fp16 O into [B, N, C] ----
    const float inv0 = 1.f / l0r, inv1 = 1.f / l1r;
    const int b = bh >> 4, h = bh & 15;
    #pragma unroll
    for (int hf = 0; hf < 2; hf++) {
        int n = q0 + w * 16 + (lane >> 2) + hf * 8;
        float inv = hf ? inv1 : inv0;
        __half* orow = Oh + ((size_t)b * NSEQ + n) * CC;
        #pragma unroll
        for (int nt = 0; nt < 8; nt++) {
            int col = h * 64 + nt * 8 + (lane & 3) * 2;
            float o0 = oacc[nt][hf * 2 + 0] * inv;
            float o1 = oacc[nt][hf * 2 + 1] * inv;
            *(__half2*)&orow[col] = __float22half2_rn(make_float2(o0, o1));
        }
    }
}

// ---------------------------------------------------------------------------
// Launcher
// ---------------------------------------------------------------------------
extern "C" void kernel_launch(void* const* d_in, const int* in_sizes, int n_in,
                              void* d_out, int out_size)
{
    const float* x     = (const float*)d_in[0];
    const float* W_qkv = (const float*)d_in[1];
    const float* b_qkv = (const float*)d_in[2];
    const float* W_out = (const float*)d_in[3];
    const float* b_out = (const float*)d_in[4];
    float* out = (float*)d_out;

    __half *qh, *kh, *vh, *Abuf, *Oh, *Bq, *Bo;
    cudaGetSymbolAddress((void**)&qh,   g_qh);
    cudaGetSymbolAddress((void**)&kh,   g_kh);
    cudaGetSymbolAddress((void**)&vh,   g_vh);
    cudaGetSymbolAddress((void**)&Abuf, g_Abuf);
    cudaGetSymbolAddress((void**)&Oh,   g_Oh);
    cudaGetSymbolAddress((void**)&Bq,   g_Bq);
    cudaGetSymbolAddress((void**)&Bo,   g_Bo);

    cudaFuncSetAttribute((const void*)mma_gemm_kernel<0, GK2>,
                         cudaFuncAttributeMaxDynamicSharedMemorySize, GEMM_SMEM);
    cudaFuncSetAttribute((const void*)mma_gemm_kernel<1, CC>,
                         cudaFuncAttributeMaxDynamicSharedMemorySize, GEMM_SMEM);
    cudaFuncSetAttribute(flash_mma_kernel,
                         cudaFuncAttributeMaxDynamicSharedMemorySize, FL_SMEM);

    // 1) split x -> x' [hi|lo] fp16
    split_x_kernel<<<MM * 512 / 256, 256>>>(x, Abuf);
    // 2) transpose weights -> K-major fp16 ([hi;hi] for qkv, plain for out)
    {
        dim3 blk(32, 8);
        transw_kernel<1><<<dim3(CC / 32, K3 / 32), blk>>>(W_qkv, Bq, K3, GK2);
        transw_kernel<0><<<dim3(CC / 32, CC / 32), blk>>>(W_out, Bo, CC, CC);
    }
    // 3) QKV projection (HMMA fp16x2) -> fp16 Q(scaled)/K/V
    mma_gemm_kernel<0, GK2><<<dim3(K3 / 128, MM / 128), 256, GEMM_SMEM>>>(
        Abuf, Bq, b_qkv, nullptr, qh, kh, vh);
    // 4) Flash attention (fp16 HMMA, occ 2) -> Oh [B,N,C] fp16
    flash_mma_kernel<<<dim3(NSEQ / 128, BB * HH), 256, FL_SMEM>>>(qh, kh, vh, Oh);
    // 5) Output projection (HMMA fp16, K=1024) -> out
    mma_gemm_kernel<1, CC><<<dim3(CC / 128, MM / 128), 256, GEMM_SMEM>>>(
        Oh, Bo, b_out, out, nullptr, nullptr, nullptr);
}

// round 6
// speedup vs baseline: 7.8539x; 1.2652x over previous
#include <cuda_runtime.h>
#include <cuda_fp16.h>
#include <math.h>
#include <stdint.h>

#define BB 2
#define HH 16
#define NSEQ 2048
#define DD 64
#define CC 1024
#define MM (BB*NSEQ)      /* 4096 */
#define K3 (3*CC)         /* 3072 */

// ---------------------------------------------------------------------------
// Scratch (__device__ globals; allocation-free rule)
// ---------------------------------------------------------------------------
__device__ __align__(256) __half g_qh[(size_t)BB*HH*NSEQ*DD];   // Q fp16, pre-scaled 0.125
__device__ __align__(256) __half g_kh[(size_t)BB*HH*NSEQ*DD];
__device__ __align__(256) __half g_vh[(size_t)BB*HH*NSEQ*DD];
__device__ __align__(256) __half g_xh[(size_t)MM*CC];           // x cast to fp16
__device__ __align__(256) __half g_Oh[(size_t)MM*CC];           // attention out, fp16
__device__ __align__(256) __half g_Bq[(size_t)K3*CC];           // W_qkv fp16 K-major
__device__ __align__(256) __half g_Bo[(size_t)CC*CC];           // W_out fp16 K-major

// ---------------------------------------------------------------------------
// PTX helpers (baseline sm_80 ISA — safe on plain sm_103 target)
// ---------------------------------------------------------------------------
__device__ __forceinline__ uint32_t smem_u32(const void* p) {
    uint32_t a;
    asm("{ .reg .u64 t; cvta.to.shared.u64 t, %1; cvt.u32.u64 %0, t; }"
        : "=r"(a) : "l"(p));
    return a;
}

#define SW128(off) ((off) ^ (((off) >> 3) & 0x70))

#define CP16(dst, src) \
    asm volatile("cp.async.cg.shared.global [%0], [%1], 16;" :: "r"(dst), "l"(src))
#define CP_COMMIT() asm volatile("cp.async.commit_group;" ::: "memory")
#define CP_WAIT0()  asm volatile("cp.async.wait_group 0;" ::: "memory")
#define CP_WAIT1()  asm volatile("cp.async.wait_group 1;" ::: "memory")

__device__ __forceinline__ void ldsm4(uint32_t& r0, uint32_t& r1,
                                      uint32_t& r2, uint32_t& r3, uint32_t a) {
    asm volatile("ldmatrix.sync.aligned.m8n8.x4.shared.b16 {%0,%1,%2,%3}, [%4];"
        : "=r"(r0), "=r"(r1), "=r"(r2), "=r"(r3) : "r"(a));
}
__device__ __forceinline__ void ldsm2t(uint32_t& r0, uint32_t& r1, uint32_t a) {
    asm volatile("ldmatrix.sync.aligned.m8n8.x2.trans.shared.b16 {%0,%1}, [%2];"
        : "=r"(r0), "=r"(r1) : "r"(a));
}
__device__ __forceinline__ void mma_f16(float* c, const uint32_t* a, uint32_t b0, uint32_t b1) {
    asm volatile("mma.sync.aligned.m16n8k16.row.col.f32.f16.f16.f32 "
        "{%0,%1,%2,%3}, {%4,%5,%6,%7}, {%8,%9}, {%0,%1,%2,%3};"
        : "+f"(c[0]), "+f"(c[1]), "+f"(c[2]), "+f"(c[3])
        : "r"(a[0]), "r"(a[1]), "r"(a[2]), "r"(a[3]), "r"(b0), "r"(b1));
}

__device__ __forceinline__ uint32_t pack_h2(float lo, float hi) {
    __half2 h = __float22half2_rn(make_float2(lo, hi));
    return *(uint32_t*)&h;
}

// ---------------------------------------------------------------------------
// Prep: cast fp32 [M][1024] -> fp16 [M][1024]
// ---------------------------------------------------------------------------
__global__ __launch_bounds__(256) void cast_x_kernel(
    const float* __restrict__ in, __half* __restrict__ out)
{
    int idx = blockIdx.x * 256 + threadIdx.x;   // one per 4 floats; grid exact
    float4 v = *(const float4*)&in[(size_t)idx * 4];
    __half2 a = __float22half2_rn(make_float2(v.x, v.y));
    __half2 b = __float22half2_rn(make_float2(v.z, v.w));
    *(uint2*)&out[(size_t)idx * 4] = make_uint2(*(uint32_t*)&a, *(uint32_t*)&b);
}

// ---------------------------------------------------------------------------
// Prep: W [1024][N] fp32 -> B' [N][1024] fp16 K-major (transpose + cast)
// ---------------------------------------------------------------------------
__global__ void transw_kernel(const float* __restrict__ W,
                              __half* __restrict__ Bo, int N)
{
    __shared__ float t[32][33];
    int k0 = blockIdx.x * 32, n0 = blockIdx.y * 32;
    int tx = threadIdx.x, ty = threadIdx.y;   // (32, 8)
    #pragma unroll
    for (int i = 0; i < 4; i++)
        t[ty + i * 8][tx] = W[(size_t)(k0 + ty + i * 8) * N + n0 + tx];
    __syncthreads();
    #pragma unroll
    for (int i = 0; i < 4; i++) {
        int n = n0 + ty + i * 8, k = k0 + tx;
        Bo[(size_t)n * CC + k] = __float2half_rn(t[tx][ty + i * 8]);
    }
}

// ---------------------------------------------------------------------------
// HMMA GEMM: D[M][N] = A[M][1024] @ B[N][1024]^T (+bias)
// BM=128, BN=128, BK=64, 3-stage cp.async, 1 sync/iter, 2 CTAs/SM.
// 8 warps: 4(m) x 2(n) -> warp tile 32x64.
// MODE 0: qkv — fp16 to Qh/Kh/Vh in [b,h,n,d], Q pre-scaled 0.125.
// MODE 1: out proj — fp32 + bias to Cout.
// ---------------------------------------------------------------------------
#define STAGE_BYTES 32768
#define GEMM_SMEM (3 * STAGE_BYTES + 128)
#define KEXT 1024
#define KITERS (KEXT / 64)

template<int MODE>
__global__ __launch_bounds__(256, 2) void mma_gemm_kernel(
    const __half* __restrict__ A,
    const __half* __restrict__ Bm,
    const float* __restrict__ bias,
    float* __restrict__ Cout,
    __half* __restrict__ Qh, __half* __restrict__ Kh, __half* __restrict__ Vh)
{
    extern __shared__ char smraw[];
    char* smp = (char*)(((uintptr_t)smraw + 127) & ~(uintptr_t)127);
    const uint32_t sb = smem_u32(smp);

    const int tid = threadIdx.x;
    const int lane = tid & 31, wid = tid >> 5;
    const int wm = wid & 3, wn = wid >> 2;
    const int m0 = blockIdx.y * 128;
    const int n0 = blockIdx.x * 128;

    const char* gA = (const char*)A + (size_t)m0 * (KEXT * 2);
    const char* gB = (const char*)Bm + (size_t)n0 * (KEXT * 2);

    const int crow = tid >> 3;           // 0..31, +32 per i
    const int ccol = (tid & 7) * 16;

    auto load_tile = [&](int it, int buf) {
        const uint32_t ao = (uint32_t)buf * STAGE_BYTES;
        const uint32_t bo = ao + 16384u;
        const size_t kbyte = (size_t)it * 128;
        #pragma unroll
        for (int i = 0; i < 4; i++) {
            int r = crow + i * 32;
            CP16(sb + ao + SW128(r * 128 + ccol),
                 gA + (size_t)r * (KEXT * 2) + kbyte + ccol);
        }
        #pragma unroll
        for (int i = 0; i < 4; i++) {
            int r = crow + i * 32;
            CP16(sb + bo + SW128(r * 128 + ccol),
                 gB + (size_t)r * (KEXT * 2) + kbyte + ccol);
        }
    };

    float acc[2][8][4];
    #pragma unroll
    for (int mt = 0; mt < 2; mt++)
        #pragma unroll
        for (int nt = 0; nt < 8; nt++)
            #pragma unroll
            for (int j = 0; j < 4; j++) acc[mt][nt][j] = 0.f;

    load_tile(0, 0); CP_COMMIT();
    load_tile(1, 1); CP_COMMIT();

    int buf = 0;
    for (int it = 0; it < KITERS; it++) {
        CP_WAIT1();
        __syncthreads();
        if (it + 2 < KITERS) load_tile(it + 2, (buf + 2) % 3);
        CP_COMMIT();   // unconditional keeps wait_group 1 uniform

        const uint32_t ao = (uint32_t)buf * STAGE_BYTES;
        const uint32_t bo = ao + 16384u;

        #pragma unroll
        for (int ks = 0; ks < 4; ks++) {
            uint32_t a[2][4];
            #pragma unroll
            for (int mt = 0; mt < 2; mt++) {
                uint32_t addr = sb + ao +
                    SW128((wm * 32 + mt * 16 + (lane & 15)) * 128 +
                          ks * 32 + ((lane >> 4) << 4));
                ldsm4(a[mt][0], a[mt][1], a[mt][2], a[mt][3], addr);
            }
            uint32_t b[8][2];
            #pragma unroll
            for (int p = 0; p < 4; p++) {
                uint32_t addr = sb + bo +
                    SW128((wn * 64 + p * 16 + (lane & 7) + ((lane >> 4) & 1) * 8) * 128 +
                          ks * 32 + ((lane >> 3) & 1) * 16);
                ldsm4(b[2 * p][0], b[2 * p][1], b[2 * p + 1][0], b[2 * p + 1][1], addr);
            }
            #pragma unroll
            for (int mt = 0; mt < 2; mt++)
                #pragma unroll
                for (int nt = 0; nt < 8; nt++)
                    mma_f16(acc[mt][nt], a[mt], b[nt][0], b[nt][1]);
        }
        buf = (buf + 1) % 3;
    }

    // ---------------- epilogue ----------------
    const int colbase = n0 + wn * 64;    // 64-aligned -> single head per warp
    if (MODE == 0) {
        const int s = colbase >> 10;
        const int h = (colbase >> 6) & 15;
        __half* dst = (s == 0) ? Qh : ((s == 1) ? Kh : Vh);
        const float scl = (s == 0) ? 0.125f : 1.0f;
        #pragma unroll
        for (int mt = 0; mt < 2; mt++) {
            #pragma unroll
            for (int hf = 0; hf < 2; hf++) {
                int r = m0 + wm * 32 + mt * 16 + (lane >> 2) + hf * 8;
                int bidx = r >> 11, n = r & (NSEQ - 1);
                size_t rowoff = (((size_t)bidx * HH + h) * NSEQ + n) * DD;
                #pragma unroll
                for (int nt = 0; nt < 8; nt++) {
                    int dd = nt * 8 + (lane & 3) * 2;
                    float v0 = (acc[mt][nt][hf * 2 + 0] + bias[colbase + dd]) * scl;
                    float v1 = (acc[mt][nt][hf * 2 + 1] + bias[colbase + dd + 1]) * scl;
                    *(__half2*)&dst[rowoff + dd] =
                        __float22half2_rn(make_float2(v0, v1));
                }
            }
        }
    } else {
        #pragma unroll
        for (int mt = 0; mt < 2; mt++) {
            #pragma unroll
            for (int hf = 0; hf < 2; hf++) {
                int r = m0 + wm * 32 + mt * 16 + (lane >> 2) + hf * 8;
                float* crow = &Cout[(size_t)r * CC];
                #pragma unroll
                for (int nt = 0; nt < 8; nt++) {
                    int cc = colbase + nt * 8 + (lane & 3) * 2;
                    float2 o;
                    o.x = acc[mt][nt][hf * 2 + 0] + bias[cc];
                    o.y = acc[mt][nt][hf * 2 + 1] + bias[cc + 1];
                    *(float2*)&crow[cc] = o;
                }
            }
        }
    }
}

// ---------------------------------------------------------------------------
// Flash attention, fp16 HMMA, 2 CTAs/SM. Per CTA: 128 q-rows of one (b,h);
// 8 warps, warp = 16 q-rows. Q pre-scaled by 1/sqrt(d).
// Epilogue writes fp16 O directly into [B,N,C] (out-proj A input).
// ---------------------------------------------------------------------------
#define FL_SMEM (49152 + 128)

__global__ __launch_bounds__(256, 2) void flash_mma_kernel(
    const __half* __restrict__ Qh, const __half* __restrict__ Kh,
    const __half* __restrict__ Vh, __half* __restrict__ Oh)
{
    extern __shared__ char smraw[];
    char* smp = (char*)(((uintptr_t)smraw + 127) & ~(uintptr_t)127);
    const uint32_t sb = smem_u32(smp);
    const uint32_t sQ = 0, sK[2] = {16384u, 24576u}, sV[2] = {32768u, 40960u};

    const int tid = threadIdx.x;
    const int lane = tid & 31, w = tid >> 5;
    const int bh = blockIdx.y;
    const int q0 = blockIdx.x * 128;
    const size_t base = (size_t)bh * NSEQ * DD;

    const char* gK = (const char*)(Kh + base);
    const char* gV = (const char*)(Vh + base);
    const int crow = tid >> 3;
    const int ccol = (tid & 7) * 16;

    // Q tile 128x64 fp16 via cp.async
    {
        const char* gQ = (const char*)(Qh + base + (size_t)q0 * DD);
        #pragma unroll
        for (int i = 0; i < 4; i++) {
            int r = crow + i * 32;
            CP16(sb + sQ + SW128(r * 128 + ccol), gQ + (size_t)r * 128 + ccol);
        }
    }

    auto load_kv = [&](int kc, int buf) {
        const size_t rb = (size_t)kc * 64 * 128;
        #pragma unroll
        for (int i = 0; i < 2; i++) {
            int r = crow + i * 32;
            CP16(sb + sK[buf] + SW128(r * 128 + ccol), gK + rb + (size_t)r * 128 + ccol);
        }
        #pragma unroll
        for (int i = 0; i < 2; i++) {
            int r = crow + i * 32;
            CP16(sb + sV[buf] + SW128(r * 128 + ccol), gV + rb + (size_t)r * 128 + ccol);
        }
    };

    load_kv(0, 0);
    CP_COMMIT();

    float oacc[8][4];
    #pragma unroll
    for (int nt = 0; nt < 8; nt++)
        #pragma unroll
        for (int j = 0; j < 4; j++) oacc[nt][j] = 0.f;
    float m0r = -1e30f, m1r = -1e30f, l0r = 0.f, l1r = 0.f;

    for (int kc = 0; kc < NSEQ / 64; kc++) {
        CP_WAIT0();
        __syncthreads();
        if (kc + 1 < NSEQ / 64) {
            load_kv(kc + 1, (kc + 1) & 1);
            CP_COMMIT();
        }
        const int buf = kc & 1;

        // ---- S = Q @ K^T (pre-scaled) ----
        float sacc[8][4];
        #pragma unroll
        for (int nt = 0; nt < 8; nt++)
            #pragma unroll
            for (int j = 0; j < 4; j++) sacc[nt][j] = 0.f;

        #pragma unroll
        for (int ks = 0; ks < 4; ks++) {
            uint32_t a[4];
            ldsm4(a[0], a[1], a[2], a[3],
                  sb + sQ + SW128((w * 16 + (lane & 15)) * 128 +
                                  ks * 32 + ((lane >> 4) << 4)));
            #pragma unroll
            for (int p = 0; p < 4; p++) {
                uint32_t b0, b1, b2, b3;
                ldsm4(b0, b1, b2, b3,
                      sb + sK[buf] + SW128((p * 16 + (lane & 7) + ((lane >> 4) & 1) * 8) * 128 +
                                           ks * 32 + ((lane >> 3) & 1) * 16));
                mma_f16(sacc[2 * p], a, b0, b1);
                mma_f16(sacc[2 * p + 1], a, b2, b3);
            }
        }

        // ---- online softmax ----
        float mx0 = m0r, mx1 = m1r;
        #pragma unroll
        for (int nt = 0; nt < 8; nt++) {
            mx0 = fmaxf(mx0, fmaxf(sacc[nt][0], sacc[nt][1]));
            mx1 = fmaxf(mx1, fmaxf(sacc[nt][2], sacc[nt][3]));
        }
        mx0 = fmaxf(mx0, __shfl_xor_sync(0xffffffffu, mx0, 1));
        mx0 = fmaxf(mx0, __shfl_xor_sync(0xffffffffu, mx0, 2));
        mx1 = fmaxf(mx1, __shfl_xor_sync(0xffffffffu, mx1, 1));
        mx1 = fmaxf(mx1, __shfl_xor_sync(0xffffffffu, mx1, 2));

        float alpha0 = __expf(m0r - mx0);
        float alpha1 = __expf(m1r - mx1);
        m0r = mx0; m1r = mx1;

        float rs0 = 0.f, rs1 = 0.f;
        #pragma unroll
        for (int nt = 0; nt < 8; nt++) {
            sacc[nt][0] = __expf(sacc[nt][0] - mx0);
            sacc[nt][1] = __expf(sacc[nt][1] - mx0);
            sacc[nt][2] = __expf(sacc[nt][2] - mx1);
            sacc[nt][3] = __expf(sacc[nt][3] - mx1);
            rs0 += sacc[nt][0] + sacc[nt][1];
            rs1 += sacc[nt][2] + sacc[nt][3];
        }
        rs0 += __shfl_xor_sync(0xffffffffu, rs0, 1);
        rs0 += __shfl_xor_sync(0xffffffffu, rs0, 2);
        rs1 += __shfl_xor_sync(0xffffffffu, rs1, 1);
        rs1 += __shfl_xor_sync(0xffffffffu, rs1, 2);
        l0r = l0r * alpha0 + rs0;
        l1r = l1r * alpha1 + rs1;

        #pragma unroll
        for (int nt = 0; nt < 8; nt++) {
            oacc[nt][0] *= alpha0; oacc[nt][1] *= alpha0;
            oacc[nt][2] *= alpha1; oacc[nt][3] *= alpha1;
        }

        // ---- O += P @ V ----
        #pragma unroll
        for (int kt = 0; kt < 4; kt++) {
            uint32_t pa[4];
            pa[0] = pack_h2(sacc[2 * kt][0],     sacc[2 * kt][1]);
            pa[1] = pack_h2(sacc[2 * kt][2],     sacc[2 * kt][3]);
            pa[2] = pack_h2(sacc[2 * kt + 1][0], sacc[2 * kt + 1][1]);
            pa[3] = pack_h2(sacc[2 * kt + 1][2], sacc[2 * kt + 1][3]);
            #pragma unroll
            for (int nt = 0; nt < 8; nt++) {
                uint32_t v0, v1;
                ldsm2t(v0, v1,
                       sb + sV[buf] + SW128((kt * 16 + (lane & 15)) * 128 + nt * 16));
                mma_f16(oacc[nt], pa, v0, v1);
            }
        }
        __syncthreads();
    }

    // ---- epilogue: fp16 O into [B, N, C] ----
    const float inv0 = 1.f / l0r, inv1 = 1.f / l1r;
    const int b = bh >> 4, h = bh & 15;
    #pragma unroll
    for (int hf = 0; hf < 2; hf++) {
        int n = q0 + w * 16 + (lane >> 2) + hf * 8;
        float inv = hf ? inv1 : inv0;
        __half* orow = Oh + ((size_t)b * NSEQ + n) * CC;
        #pragma unroll
        for (int nt = 0; nt < 8; nt++) {
            int col = h * 64 + nt * 8 + (lane & 3) * 2;
            float o0 = oacc[nt][hf * 2 + 0] * inv;
            float o1 = oacc[nt][hf * 2 + 1] * inv;
            *(__half2*)&orow[col] = __float22half2_rn(make_float2(o0, o1));
        }
    }
}

// ---------------------------------------------------------------------------
// Launcher
// ---------------------------------------------------------------------------
extern "C" void kernel_launch(void* const* d_in, const int* in_sizes, int n_in,
                              void* d_out, int out_size)
{
    const float* x     = (const float*)d_in[0];
    const float* W_qkv = (const float*)d_in[1];
    const float* b_qkv = (const float*)d_in[2];
    const float* W_out = (const float*)d_in[3];
    const float* b_out = (const float*)d_in[4];
    float* out = (float*)d_out;

    __half *qh, *kh, *vh, *xh, *Oh, *Bq, *Bo;
    cudaGetSymbolAddress((void**)&qh, g_qh);
    cudaGetSymbolAddress((void**)&kh, g_kh);
    cudaGetSymbolAddress((void**)&vh, g_vh);
    cudaGetSymbolAddress((void**)&xh, g_xh);
    cudaGetSymbolAddress((void**)&Oh, g_Oh);
    cudaGetSymbolAddress((void**)&Bq, g_Bq);
    cudaGetSymbolAddress((void**)&Bo, g_Bo);

    cudaFuncSetAttribute((const void*)mma_gemm_kernel<0>,
                         cudaFuncAttributeMaxDynamicSharedMemorySize, GEMM_SMEM);
    cudaFuncSetAttribute((const void*)mma_gemm_kernel<1>,
                         cudaFuncAttributeMaxDynamicSharedMemorySize, GEMM_SMEM);
    cudaFuncSetAttribute(flash_mma_kernel,
                         cudaFuncAttributeMaxDynamicSharedMemorySize, FL_SMEM);

    // 1) cast x -> fp16
    cast_x_kernel<<<MM * CC / 4 / 256, 256>>>(x, xh);
    // 2) transpose+cast weights -> K-major fp16
    {
        dim3 blk(32, 8);
        transw_kernel<<<dim3(CC / 32, K3 / 32), blk>>>(W_qkv, Bq, K3);
        transw_kernel<<<dim3(CC / 32, CC / 32), blk>>>(W_out, Bo, CC);
    }
    // 3) QKV projection (HMMA fp16, K=1024) -> fp16 Q(scaled)/K/V
    mma_gemm_kernel<0><<<dim3(K3 / 128, MM / 128), 256, GEMM_SMEM>>>(
        xh, Bq, b_qkv, nullptr, qh, kh, vh);
    // 4) Flash attention (fp16 HMMA, occ 2) -> Oh [B,N,C] fp16
    flash_mma_kernel<<<dim3(NSEQ / 128, BB * HH), 256, FL_SMEM>>>(qh, kh, vh, Oh);
    // 5) Output projection (HMMA fp16, K=1024) -> out
    mma_gemm_kernel<1><<<dim3(CC / 128, MM / 128), 256, GEMM_SMEM>>>(
        Oh, Bo, b_out, out, nullptr, nullptr, nullptr);
}

// round 7
// speedup vs baseline: 8.4573x; 1.0768x over previous
#include <cuda_runtime.h>
#include <cuda_fp16.h>
#include <math.h>
#include <stdint.h>

#define BB 2
#define HH 16
#define NSEQ 2048
#define DD 64
#define CC 1024
#define MM (BB*NSEQ)      /* 4096 */
#define K3 (3*CC)         /* 3072 */

// ---------------------------------------------------------------------------
// Scratch (__device__ globals; allocation-free rule)
// ---------------------------------------------------------------------------
__device__ __align__(256) __half g_qh[(size_t)BB*HH*NSEQ*DD];   // Q fp16, pre-scaled 0.125*log2e
__device__ __align__(256) __half g_kh[(size_t)BB*HH*NSEQ*DD];
__device__ __align__(256) __half g_vh[(size_t)BB*HH*NSEQ*DD];
__device__ __align__(256) __half g_xh[(size_t)MM*CC];           // x cast to fp16
__device__ __align__(256) __half g_Oh[(size_t)MM*CC];           // attention out, fp16
__device__ __align__(256) __half g_Bq[(size_t)K3*CC];           // W_qkv fp16 K-major
__device__ __align__(256) __half g_Bo[(size_t)CC*CC];           // W_out fp16 K-major

// ---------------------------------------------------------------------------
// PTX helpers (baseline sm_80 ISA — safe on plain sm_103 target)
// ---------------------------------------------------------------------------
__device__ __forceinline__ uint32_t smem_u32(const void* p) {
    uint32_t a;
    asm("{ .reg .u64 t; cvta.to.shared.u64 t, %1; cvt.u32.u64 %0, t; }"
        : "=r"(a) : "l"(p));
    return a;
}

#define SW128(off) ((off) ^ (((off) >> 3) & 0x70))

#define CP16(dst, src) \
    asm volatile("cp.async.cg.shared.global [%0], [%1], 16;" :: "r"(dst), "l"(src))
#define CP_COMMIT() asm volatile("cp.async.commit_group;" ::: "memory")
#define CP_WAIT1()  asm volatile("cp.async.wait_group 1;" ::: "memory")

__device__ __forceinline__ void ldsm4(uint32_t& r0, uint32_t& r1,
                                      uint32_t& r2, uint32_t& r3, uint32_t a) {
    asm volatile("ldmatrix.sync.aligned.m8n8.x4.shared.b16 {%0,%1,%2,%3}, [%4];"
        : "=r"(r0), "=r"(r1), "=r"(r2), "=r"(r3) : "r"(a));
}
__device__ __forceinline__ void ldsm2t(uint32_t& r0, uint32_t& r1, uint32_t a) {
    asm volatile("ldmatrix.sync.aligned.m8n8.x2.trans.shared.b16 {%0,%1}, [%2];"
        : "=r"(r0), "=r"(r1) : "r"(a));
}
__device__ __forceinline__ void mma_f16(float* c, const uint32_t* a, uint32_t b0, uint32_t b1) {
    asm volatile("mma.sync.aligned.m16n8k16.row.col.f32.f16.f16.f32 "
        "{%0,%1,%2,%3}, {%4,%5,%6,%7}, {%8,%9}, {%0,%1,%2,%3};"
        : "+f"(c[0]), "+f"(c[1]), "+f"(c[2]), "+f"(c[3])
        : "r"(a[0]), "r"(a[1]), "r"(a[2]), "r"(a[3]), "r"(b0), "r"(b1));
}

__device__ __forceinline__ uint32_t pack_h2(float lo, float hi) {
    __half2 h = __float22half2_rn(make_float2(lo, hi));
    return *(uint32_t*)&h;
}
__device__ __forceinline__ uint32_t ex2_h2(uint32_t x) {
    uint32_t r;
    asm("ex2.approx.f16x2 %0, %1;" : "=r"(r) : "r"(x));
    return r;
}
__device__ __forceinline__ float ex2_f32(float x) {
    float r;
    asm("ex2.approx.f32 %0, %1;" : "=f"(r) : "f"(x));
    return r;
}

// ---------------------------------------------------------------------------
// Fused prep: cast x->fp16, transpose+cast both weight matrices.
// grid partitioned by blockIdx.x; 256 threads.
// ---------------------------------------------------------------------------
#define NB_CAST (MM * CC / 1024)          /* 4096 */
#define NB_TQ   ((CC / 32) * (K3 / 32))   /* 3072 */
#define NB_TO   ((CC / 32) * (CC / 32))   /* 1024 */

__global__ __launch_bounds__(256) void prep_kernel(
    const float* __restrict__ x,  const float* __restrict__ Wq,
    const float* __restrict__ Wo, __half* __restrict__ xh,
    __half* __restrict__ Bq, __half* __restrict__ Bo)
{
    const int bid = blockIdx.x, tid = threadIdx.x;
    if (bid < NB_CAST) {
        size_t idx4 = ((size_t)bid * 256 + tid) * 4;
        float4 v = *(const float4*)&x[idx4];
        __half2 a = __float22half2_rn(make_float2(v.x, v.y));
        __half2 b = __float22half2_rn(make_float2(v.z, v.w));
        *(uint2*)&xh[idx4] = make_uint2(*(uint32_t*)&a, *(uint32_t*)&b);
        return;
    }
    // transpose: 32x32 tile, tx = n index, ty = k index
    const float* W; __half* Bd; int N, b;
    if (bid < NB_CAST + NB_TQ) { b = bid - NB_CAST; W = Wq; Bd = Bq; N = K3; }
    else                       { b = bid - NB_CAST - NB_TQ; W = Wo; Bd = Bo; N = CC; }
    const int k0 = (b % 32) * 32;
    const int n0 = (b / 32) * 32;
    const int tx = tid & 31, ty = tid >> 5;   // tx in [0,32), ty in [0,8)

    __shared__ float t[32][33];
    #pragma unroll
    for (int i = 0; i < 4; i++)
        t[ty + i * 8][tx] = W[(size_t)(k0 + ty + i * 8) * N + n0 + tx];
    __syncthreads();
    #pragma unroll
    for (int i = 0; i < 4; i++) {
        int n = n0 + ty + i * 8, k = k0 + tx;
        Bd[(size_t)n * CC + k] = __float2half_rn(t[tx][ty + i * 8]);
    }
}

// ---------------------------------------------------------------------------
// HMMA GEMM: D[M][N] = A[M][1024] @ B[N][1024]^T (+bias)
// BM=128, BN=128, BK=64, 3-stage cp.async, 1 sync/iter, 2 CTAs/SM.
// MODE 0: qkv — fp16 to Qh/Kh/Vh in [b,h,n,d], Q pre-scaled 0.125*log2e.
// MODE 1: out proj — fp32 + bias to Cout.
// ---------------------------------------------------------------------------
#define STAGE_BYTES 32768
#define GEMM_SMEM (3 * STAGE_BYTES + 128)
#define KEXT 1024
#define KITERS (KEXT / 64)
#define QSCALE 0.18033688f   /* 0.125 * log2(e) */

template<int MODE>
__global__ __launch_bounds__(256, 2) void mma_gemm_kernel(
    const __half* __restrict__ A,
    const __half* __restrict__ Bm,
    const float* __restrict__ bias,
    float* __restrict__ Cout,
    __half* __restrict__ Qh, __half* __restrict__ Kh, __half* __restrict__ Vh)
{
    extern __shared__ char smraw[];
    char* smp = (char*)(((uintptr_t)smraw + 127) & ~(uintptr_t)127);
    const uint32_t sb = smem_u32(smp);

    const int tid = threadIdx.x;
    const int lane = tid & 31, wid = tid >> 5;
    const int wm = wid & 3, wn = wid >> 2;
    const int m0 = blockIdx.y * 128;
    const int n0 = blockIdx.x * 128;

    const char* gA = (const char*)A + (size_t)m0 * (KEXT * 2);
    const char* gB = (const char*)Bm + (size_t)n0 * (KEXT * 2);

    const int crow = tid >> 3;
    const int ccol = (tid & 7) * 16;

    auto load_tile = [&](int it, int buf) {
        const uint32_t ao = (uint32_t)buf * STAGE_BYTES;
        const uint32_t bo = ao + 16384u;
        const size_t kbyte = (size_t)it * 128;
        #pragma unroll
        for (int i = 0; i < 4; i++) {
            int r = crow + i * 32;
            CP16(sb + ao + SW128(r * 128 + ccol),
                 gA + (size_t)r * (KEXT * 2) + kbyte + ccol);
        }
        #pragma unroll
        for (int i = 0; i < 4; i++) {
            int r = crow + i * 32;
            CP16(sb + bo + SW128(r * 128 + ccol),
                 gB + (size_t)r * (KEXT * 2) + kbyte + ccol);
        }
    };

    float acc[2][8][4];
    #pragma unroll
    for (int mt = 0; mt < 2; mt++)
        #pragma unroll
        for (int nt = 0; nt < 8; nt++)
            #pragma unroll
            for (int j = 0; j < 4; j++) acc[mt][nt][j] = 0.f;

    load_tile(0, 0); CP_COMMIT();
    load_tile(1, 1); CP_COMMIT();

    int buf = 0;
    for (int it = 0; it < KITERS; it++) {
        CP_WAIT1();
        __syncthreads();
        if (it + 2 < KITERS) load_tile(it + 2, (buf + 2) % 3);
        CP_COMMIT();

        const uint32_t ao = (uint32_t)buf * STAGE_BYTES;
        const uint32_t bo = ao + 16384u;

        #pragma unroll
        for (int ks = 0; ks < 4; ks++) {
            uint32_t a[2][4];
            #pragma unroll
            for (int mt = 0; mt < 2; mt++) {
                uint32_t addr = sb + ao +
                    SW128((wm * 32 + mt * 16 + (lane & 15)) * 128 +
                          ks * 32 + ((lane >> 4) << 4));
                ldsm4(a[mt][0], a[mt][1], a[mt][2], a[mt][3], addr);
            }
            uint32_t b[8][2];
            #pragma unroll
            for (int p = 0; p < 4; p++) {
                uint32_t addr = sb + bo +
                    SW128((wn * 64 + p * 16 + (lane & 7) + ((lane >> 4) & 1) * 8) * 128 +
                          ks * 32 + ((lane >> 3) & 1) * 16);
                ldsm4(b[2 * p][0], b[2 * p][1], b[2 * p + 1][0], b[2 * p + 1][1], addr);
            }
            #pragma unroll
            for (int mt = 0; mt < 2; mt++)
                #pragma unroll
                for (int nt = 0; nt < 8; nt++)
                    mma_f16(acc[mt][nt], a[mt], b[nt][0], b[nt][1]);
        }
        buf = (buf + 1) % 3;
    }

    // ---------------- epilogue ----------------
    const int colbase = n0 + wn * 64;
    if (MODE == 0) {
        const int s = colbase >> 10;
        const int h = (colbase >> 6) & 15;
        __half* dst = (s == 0) ? Qh : ((s == 1) ? Kh : Vh);
        const float scl = (s == 0) ? QSCALE : 1.0f;
        #pragma unroll
        for (int mt = 0; mt < 2; mt++) {
            #pragma unroll
            for (int hf = 0; hf < 2; hf++) {
                int r = m0 + wm * 32 + mt * 16 + (lane >> 2) + hf * 8;
                int bidx = r >> 11, n = r & (NSEQ - 1);
                size_t rowoff = (((size_t)bidx * HH + h) * NSEQ + n) * DD;
                #pragma unroll
                for (int nt = 0; nt < 8; nt++) {
                    int dd = nt * 8 + (lane & 3) * 2;
                    float v0 = (acc[mt][nt][hf * 2 + 0] + bias[colbase + dd]) * scl;
                    float v1 = (acc[mt][nt][hf * 2 + 1] + bias[colbase + dd + 1]) * scl;
                    *(__half2*)&dst[rowoff + dd] =
                        __float22half2_rn(make_float2(v0, v1));
                }
            }
        }
    } else {
        #pragma unroll
        for (int mt = 0; mt < 2; mt++) {
            #pragma unroll
            for (int hf = 0; hf < 2; hf++) {
                int r = m0 + wm * 32 + mt * 16 + (lane >> 2) + hf * 8;
                float* crow = &Cout[(size_t)r * CC];
                #pragma unroll
                for (int nt = 0; nt < 8; nt++) {
                    int cc = colbase + nt * 8 + (lane & 3) * 2;
                    float2 o;
                    o.x = acc[mt][nt][hf * 2 + 0] + bias[cc];
                    o.y = acc[mt][nt][hf * 2 + 1] + bias[cc + 1];
                    *(float2*)&crow[cc] = o;
                }
            }
        }
    }
}

// ---------------------------------------------------------------------------
// Flash attention, fp16 HMMA, log2-domain softmax, 3-stage KV pipeline,
// Q fragments hoisted, row-sum via ones-MMA. 2 CTAs/SM.
// Per CTA: 128 q-rows of one (b,h); 8 warps, warp = 16 q-rows.
// ---------------------------------------------------------------------------
#define FL_SQ 0u
#define FL_KV(buf) (16384u + (uint32_t)(buf) * 16384u)   /* K 8KB then V 8KB */
#define FL_SMEM (65536 + 128)
#define NKB (NSEQ / 64)
#define ONES2 0x3C003C00u

__global__ __launch_bounds__(256, 2) void flash_mma_kernel(
    const __half* __restrict__ Qh, const __half* __restrict__ Kh,
    const __half* __restrict__ Vh, __half* __restrict__ Oh)
{
    extern __shared__ char smraw[];
    char* smp = (char*)(((uintptr_t)smraw + 127) & ~(uintptr_t)127);
    const uint32_t sb = smem_u32(smp);

    const int tid = threadIdx.x;
    const int lane = tid & 31, w = tid >> 5;
    const int bh = blockIdx.y;
    const int q0 = blockIdx.x * 128;
    const size_t base = (size_t)bh * NSEQ * DD;

    const char* gK = (const char*)(Kh + base);
    const char* gV = (const char*)(Vh + base);
    const int crow = tid >> 3;
    const int ccol = (tid & 7) * 16;

    auto load_kv = [&](int kc, int buf) {
        const size_t rb = (size_t)kc * 64 * 128;
        const uint32_t ko = FL_KV(buf), vo = ko + 8192u;
        #pragma unroll
        for (int i = 0; i < 2; i++) {
            int r = crow + i * 32;
            CP16(sb + ko + SW128(r * 128 + ccol), gK + rb + (size_t)r * 128 + ccol);
        }
        #pragma unroll
        for (int i = 0; i < 2; i++) {
            int r = crow + i * 32;
            CP16(sb + vo + SW128(r * 128 + ccol), gV + rb + (size_t)r * 128 + ccol);
        }
    };

    // prologue: Q + KV0 in group 0, KV1 in group 1
    {
        const char* gQ = (const char*)(Qh + base + (size_t)q0 * DD);
        #pragma unroll
        for (int i = 0; i < 4; i++) {
            int r = crow + i * 32;
            CP16(sb + FL_SQ + SW128(r * 128 + ccol), gQ + (size_t)r * 128 + ccol);
        }
    }
    load_kv(0, 0); CP_COMMIT();
    load_kv(1, 1); CP_COMMIT();

    uint32_t qf[4][4];   // Q fragments, loaded at kc==0
    float oacc[8][4];
    #pragma unroll
    for (int nt = 0; nt < 8; nt++)
        #pragma unroll
        for (int j = 0; j < 4; j++) oacc[nt][j] = 0.f;
    float m0r = -1e30f, m1r = -1e30f, l0r = 0.f, l1r = 0.f;

    int buf = 0;
    for (int kc = 0; kc < NKB; kc++) {
        CP_WAIT1();
        __syncthreads();
        if (kc + 2 < NKB) load_kv(kc + 2, (buf + 2) % 3);
        CP_COMMIT();

        if (kc == 0) {
            #pragma unroll
            for (int ks = 0; ks < 4; ks++)
                ldsm4(qf[ks][0], qf[ks][1], qf[ks][2], qf[ks][3],
                      sb + FL_SQ + SW128((w * 16 + (lane & 15)) * 128 +
                                         ks * 32 + ((lane >> 4) << 4)));
        }
        const uint32_t ko = FL_KV(buf), vo = ko + 8192u;

        // ---- S = Q @ K^T (log2-domain logits) ----
        float sacc[8][4];
        #pragma unroll
        for (int nt = 0; nt < 8; nt++)
            #pragma unroll
            for (int j = 0; j < 4; j++) sacc[nt][j] = 0.f;

        #pragma unroll
        for (int ks = 0; ks < 4; ks++) {
            #pragma unroll
            for (int p = 0; p < 4; p++) {
                uint32_t b0, b1, b2, b3;
                ldsm4(b0, b1, b2, b3,
                      sb + ko + SW128((p * 16 + (lane & 7) + ((lane >> 4) & 1) * 8) * 128 +
                                      ks * 32 + ((lane >> 3) & 1) * 16));
                mma_f16(sacc[2 * p], qf[ks], b0, b1);
                mma_f16(sacc[2 * p + 1], qf[ks], b2, b3);
            }
        }

        // ---- online softmax (log2 domain) ----
        float mx0 = m0r, mx1 = m1r;
        #pragma unroll
        for (int nt = 0; nt < 8; nt++) {
            mx0 = fmaxf(mx0, fmaxf(sacc[nt][0], sacc[nt][1]));
            mx1 = fmaxf(mx1, fmaxf(sacc[nt][2], sacc[nt][3]));
        }
        mx0 = fmaxf(mx0, __shfl_xor_sync(0xffffffffu, mx0, 1));
        mx0 = fmaxf(mx0, __shfl_xor_sync(0xffffffffu, mx0, 2));
        mx1 = fmaxf(mx1, __shfl_xor_sync(0xffffffffu, mx1, 1));
        mx1 = fmaxf(mx1, __shfl_xor_sync(0xffffffffu, mx1, 2));

        float alpha0 = ex2_f32(m0r - mx0);
        float alpha1 = ex2_f32(m1r - mx1);
        m0r = mx0; m1r = mx1;

        #pragma unroll
        for (int nt = 0; nt < 8; nt++) {
            oacc[nt][0] *= alpha0; oacc[nt][1] *= alpha0;
            oacc[nt][2] *= alpha1; oacc[nt][3] *= alpha1;
        }

        // ---- P = exp2(S - mx) in fp16; O += P @ V; rowsum via ones-MMA ----
        float ssum[4] = {0.f, 0.f, 0.f, 0.f};
        #pragma unroll
        for (int kt = 0; kt < 4; kt++) {
            uint32_t pa[4];
            pa[0] = ex2_h2(pack_h2(sacc[2 * kt][0] - mx0,     sacc[2 * kt][1] - mx0));
            pa[1] = ex2_h2(pack_h2(sacc[2 * kt][2] - mx1,     sacc[2 * kt][3] - mx1));
            pa[2] = ex2_h2(pack_h2(sacc[2 * kt + 1][0] - mx0, sacc[2 * kt + 1][1] - mx0));
            pa[3] = ex2_h2(pack_h2(sacc[2 * kt + 1][2] - mx1, sacc[2 * kt + 1][3] - mx1));
            mma_f16(ssum, pa, ONES2, ONES2);
            #pragma unroll
            for (int nt = 0; nt < 8; nt++) {
                uint32_t v0, v1;
                ldsm2t(v0, v1,
                       sb + vo + SW128((kt * 16 + (lane & 15)) * 128 + nt * 16));
                mma_f16(oacc[nt], pa, v0, v1);
            }
        }
        l0r = l0r * alpha0 + ssum[0];
        l1r = l1r * alpha1 + ssum[2];

        buf = (buf + 1) % 3;
    }

    // ---- epilogue: fp16 O into [B, N, C] ----
    const float inv0 = 1.f / l0r, inv1 = 1.f / l1r;
    const int b = bh >> 4, h = bh & 15;
    #pragma unroll
    for (int hf = 0; hf < 2; hf++) {
        int n = q0 + w * 16 + (lane >> 2) + hf * 8;
        float inv = hf ? inv1 : inv0;
        __half* orow = Oh + ((size_t)b * NSEQ + n) * CC;
        #pragma unroll
        for (int nt = 0; nt < 8; nt++) {
            int col = h * 64 + nt * 8 + (lane & 3) * 2;
            float o0 = oacc[nt][hf * 2 + 0] * inv;
            float o1 = oacc[nt][hf * 2 + 1] * inv;
            *(__half2*)&orow[col] = __float22half2_rn(make_float2(o0, o1));
        }
    }
}

// ---------------------------------------------------------------------------
// Launcher
// ---------------------------------------------------------------------------
extern "C" void kernel_launch(void* const* d_in, const int* in_sizes, int n_in,
                              void* d_out, int out_size)
{
    const float* x     = (const float*)d_in[0];
    const float* W_qkv = (const float*)d_in[1];
    const float* b_qkv = (const float*)d_in[2];
    const float* W_out = (const float*)d_in[3];
    const float* b_out = (const float*)d_in[4];
    float* out = (float*)d_out;

    __half *qh, *kh, *vh, *xh, *Oh, *Bq, *Bo;
    cudaGetSymbolAddress((void**)&qh, g_qh);
    cudaGetSymbolAddress((void**)&kh, g_kh);
    cudaGetSymbolAddress((void**)&vh, g_vh);
    cudaGetSymbolAddress((void**)&xh, g_xh);
    cudaGetSymbolAddress((void**)&Oh, g_Oh);
    cudaGetSymbolAddress((void**)&Bq, g_Bq);
    cudaGetSymbolAddress((void**)&Bo, g_Bo);

    cudaFuncSetAttribute((const void*)mma_gemm_kernel<0>,
                         cudaFuncAttributeMaxDynamicSharedMemorySize, GEMM_SMEM);
    cudaFuncSetAttribute((const void*)mma_gemm_kernel<1>,
                         cudaFuncAttributeMaxDynamicSharedMemorySize, GEMM_SMEM);
    cudaFuncSetAttribute(flash_mma_kernel,
                         cudaFuncAttributeMaxDynamicSharedMemorySize, FL_SMEM);

    // 1) fused prep: cast x; transpose+cast W_qkv, W_out
    prep_kernel<<<NB_CAST + NB_TQ + NB_TO, 256>>>(x, W_qkv, W_out, xh, Bq, Bo);
    // 2) QKV projection (HMMA fp16, K=1024) -> fp16 Q(log2-scaled)/K/V
    mma_gemm_kernel<0><<<dim3(K3 / 128, MM / 128), 256, GEMM_SMEM>>>(
        xh, Bq, b_qkv, nullptr, qh, kh, vh);
    // 3) Flash attention (fp16 HMMA, exp2 softmax) -> Oh [B,N,C] fp16
    flash_mma_kernel<<<dim3(NSEQ / 128, BB * HH), 256, FL_SMEM>>>(qh, kh, vh, Oh);
    // 4) Output projection (HMMA fp16, K=1024) -> out
    mma_gemm_kernel<1><<<dim3(CC / 128, MM / 128), 256, GEMM_SMEM>>>(
        Oh, Bo, b_out, out, nullptr, nullptr, nullptr);
}